// round 3
// baseline (speedup 1.0000x reference)
#include <cuda_runtime.h>
#include <math.h>

#define T_SEQ 256
#define BATCH 64
#define HID   256
#define NGATE 2048              // 2 dirs * 4H
#define MROWS (T_SEQ*BATCH)     // 16384
#define K0P   304               // padded input dim for layer 0 (300 -> 304)
#define NBLK  128               // persistent blocks in recurrent kernel

// ---------------- scratch (device globals; no allocation allowed) ----------------
__device__ float    g_x0[MROWS * K0P];          // embedded input, padded    (~20 MB)
__device__ float    g_wpad0[NGATE * K0P];       // padded wih0               (~2.5 MB)
__device__ float    g_gates[(size_t)MROWS * NGATE]; // input-gate projections (~134 MB, reused)
__device__ float    g_x1T[512 * MROWS];         // layer-0 output, [feat][t*64+b] (~33.5 MB)
__device__ float    g_x2T[512 * MROWS];         // layer-1 output, same layout
__device__ float    g_h[2 * 2 * HID * BATCH];   // double-buffered h: [buf][dir][j][b]
__device__ unsigned g_bar[T_SEQ];               // per-step barrier counters

// ---------------- small kernels ----------------
__global__ void k_padw(const float* __restrict__ w) {
    int n = blockIdx.x;
    float* o = g_wpad0 + n * K0P;
    const float* s = w + n * 300;
    for (int k = threadIdx.x; k < K0P; k += blockDim.x)
        o[k] = (k < 300) ? s[k] : 0.f;
}

__global__ void k_embed(const int* __restrict__ inp, const float* __restrict__ emb) {
    int m = blockIdx.x;            // m = t*64 + b
    int t = m >> 6, b = m & 63;
    int idx = inp[b * T_SEQ + t];
    const float* e = emb + (size_t)idx * 300;
    float* o = g_x0 + m * K0P;
    for (int k = threadIdx.x; k < K0P; k += blockDim.x)
        o[k] = (k < 300) ? e[k] : 0.f;
}

__global__ void k_zero() {
    int i = blockIdx.x * blockDim.x + threadIdx.x;
    if (i < 2 * 2 * HID * BATCH) g_h[i] = 0.f;
    if (i < T_SEQ) g_bar[i] = 0u;
}

// ---------------- input-projection GEMM ----------------
// C[m][n] = sum_k A[m][k] * W[n][k] + bi[n] + bh[n]       (C = g_gates, ldc = 2048)
// LAYER 0: A = g_x0 [16384][304] row-major, W = g_wpad0 [2048][304], K=304
// LAYER 1: A = g_x1T stored transposed [512][16384],   W = wih1 [2048][512], K=512
template<int LAYER>
__global__ __launch_bounds__(256) void k_gemm(const float* __restrict__ Warg,
                                              const float* __restrict__ bi,
                                              const float* __restrict__ bh) {
    constexpr bool AT  = (LAYER == 1);
    constexpr int  K   = AT ? 512 : K0P;
    constexpr int  LDA = AT ? MROWS : K0P;
    constexpr int  KT  = K >> 3;

    const float* A = AT ? g_x1T : g_x0;
    const float* W = AT ? Warg  : g_wpad0;

    __shared__ float As[2][8][128];
    __shared__ float Ws[2][8][64];

    const int tid = threadIdx.x;
    const int m0 = blockIdx.y * 128;
    const int n0 = blockIdx.x * 64;
    const int tm = tid & 15, tn = tid >> 4;

    float acc[8][4];
#pragma unroll
    for (int i = 0; i < 8; i++)
#pragma unroll
        for (int j = 0; j < 4; j++) acc[i][j] = 0.f;

    // loader setup
    int a_row = 0, a_kp = 0, a_kk = 0, a_i4 = 0;
    const float* aP;
    if (AT) {
        a_kk = tid >> 5; a_i4 = (tid & 31) << 2;
        aP = A + (size_t)a_kk * LDA + m0 + a_i4;
    } else {
        a_row = tid >> 1; a_kp = tid & 1;
        aP = A + (size_t)(m0 + a_row) * LDA + (a_kp << 2);
    }
    const int  wn = tid >> 1, wkp = tid & 1;
    const bool wact = tid < 128;
    const float* wP = W + (size_t)(n0 + wn) * K + (wkp << 2);

    // prologue: tile 0 -> smem[0]
    {
        float4 ra = *(const float4*)aP;
        if (AT) {
            *(float4*)&As[0][a_kk][a_i4] = ra;
        } else {
            As[0][(a_kp<<2)+0][a_row] = ra.x;
            As[0][(a_kp<<2)+1][a_row] = ra.y;
            As[0][(a_kp<<2)+2][a_row] = ra.z;
            As[0][(a_kp<<2)+3][a_row] = ra.w;
        }
        if (wact) {
            float4 rw = *(const float4*)wP;
            Ws[0][(wkp<<2)+0][wn] = rw.x;
            Ws[0][(wkp<<2)+1][wn] = rw.y;
            Ws[0][(wkp<<2)+2][wn] = rw.z;
            Ws[0][(wkp<<2)+3][wn] = rw.w;
        }
    }
    __syncthreads();

    int cur = 0;
#pragma unroll 1
    for (int kt = 0; kt < KT; kt++) {
        float4 ra, rw;
        const bool more = (kt + 1) < KT;
        if (more) {
            if (AT) ra = *(const float4*)(aP + (size_t)(kt + 1) * 8 * LDA);
            else    ra = *(const float4*)(aP + (kt + 1) * 8);
            if (wact) rw = *(const float4*)(wP + (kt + 1) * 8);
        }
#pragma unroll
        for (int kk = 0; kk < 8; kk++) {
            float4 a0 = *(const float4*)&As[cur][kk][tm << 2];
            float4 a1 = *(const float4*)&As[cur][kk][64 + (tm << 2)];
            float4 wv = *(const float4*)&Ws[cur][kk][tn << 2];
            float aa[8] = {a0.x, a0.y, a0.z, a0.w, a1.x, a1.y, a1.z, a1.w};
            float ww[4] = {wv.x, wv.y, wv.z, wv.w};
#pragma unroll
            for (int i = 0; i < 8; i++)
#pragma unroll
                for (int j = 0; j < 4; j++)
                    acc[i][j] += aa[i] * ww[j];
        }
        if (more) {
            const int nb = cur ^ 1;
            if (AT) {
                *(float4*)&As[nb][a_kk][a_i4] = ra;
            } else {
                As[nb][(a_kp<<2)+0][a_row] = ra.x;
                As[nb][(a_kp<<2)+1][a_row] = ra.y;
                As[nb][(a_kp<<2)+2][a_row] = ra.z;
                As[nb][(a_kp<<2)+3][a_row] = ra.w;
            }
            if (wact) {
                Ws[nb][(wkp<<2)+0][wn] = rw.x;
                Ws[nb][(wkp<<2)+1][wn] = rw.y;
                Ws[nb][(wkp<<2)+2][wn] = rw.z;
                Ws[nb][(wkp<<2)+3][wn] = rw.w;
            }
            __syncthreads();
            cur = nb;
        }
    }

    // epilogue: add fused bias, write gates
    const int nbase = n0 + (tn << 2);
    float4 b4;
    b4.x = bi[nbase + 0] + bh[nbase + 0];
    b4.y = bi[nbase + 1] + bh[nbase + 1];
    b4.z = bi[nbase + 2] + bh[nbase + 2];
    b4.w = bi[nbase + 3] + bh[nbase + 3];
#pragma unroll
    for (int i = 0; i < 8; i++) {
        int m = m0 + ((i < 4) ? ((tm << 2) + i) : (64 + (tm << 2) + (i - 4)));
        float4 o;
        o.x = acc[i][0] + b4.x;
        o.y = acc[i][1] + b4.y;
        o.z = acc[i][2] + b4.z;
        o.w = acc[i][3] + b4.w;
        *(float4*)&g_gates[(size_t)m * NGATE + nbase] = o;
    }
}

// ---------------- recurrent scan (persistent, 128 blocks, grid barrier per step) ----------------
__device__ __forceinline__ float sigf(float x) { return 1.f / (1.f + expf(-x)); }

__global__ __launch_bounds__(256, 1) void k_lstm(const float* __restrict__ whh, // [2048][256]
                                                 int layer) {
    extern __shared__ float sm[];
    float* w_s = sm;                       // [16][260]  (pad 260 -> conflict-free w reads)
    float* h_s = sm + 16 * 260;            // [256][64]
    float* a_s = h_s + 256 * 64;           // [16][64]
    float* c_s = a_s + 16 * 64;            // [4][64]

    const float* gates = g_gates;
    float* xT = layer ? g_x2T : g_x1T;

    const int tid = threadIdx.x;
    const int bid = blockIdx.x;
    const int dir = bid >> 6;              // 0/1
    const int j0  = (bid & 63) << 2;       // 4 hidden units per block

    // load this block's recurrent-weight slice once (16 gate rows x 256)
    for (int i = tid; i < 16 * 256; i += 256) {
        int r = i >> 8, k = i & 255;
        int gg = (r & 3) * HID + j0 + (r >> 2);  // gate-major (i,f,g,o) PyTorch order
        w_s[r * 260 + k] = whh[(size_t)(dir * 1024 + gg) * HID + k];
    }
    c_s[tid] = 0.f;   // 4*64 = 256 cells
    __syncthreads();

    // dot-product thread mapping: warp = 4 rows x 32 batches
    const int w  = tid >> 5, l = tid & 31;
    const int r  = ((w & 3) << 2) | (l & 3);           // gate row 0..15
    const int bg = ((w >> 2) << 3) | (l >> 2);         // batch group 0..15 (4 batches each)
    const int gofs = dir * 1024 + (r & 3) * HID + j0 + (r >> 2);
    const float4* wrow = (const float4*)(w_s + r * 260);
    // state-update thread mapping
    const int uu = tid >> 6, bb = tid & 63;
    const int jrow = dir * HID + j0 + uu;

    for (int t = 0; t < T_SEQ; t++) {
        // load h(prev) for this dir: 16384 floats, L2-only (.cg — L1 is stale across blocks)
        const float4* hsrc = (const float4*)(g_h + (((t & 1) * 2 + dir) << 14));
        float4* hdst = (float4*)h_s;
#pragma unroll
        for (int i = 0; i < 16; i++)
            hdst[tid + (i << 8)] = __ldcg(&hsrc[tid + (i << 8)]);
        __syncthreads();

        // prefetch precomputed input-gate terms for our 4 batches
        const float* gbase = gates + (size_t)((t << 6) + (bg << 2)) * NGATE + gofs;
        float gin0 = gbase[0];
        float gin1 = gbase[NGATE];
        float gin2 = gbase[2 * NGATE];
        float gin3 = gbase[3 * NGATE];

        // 256-long dot for (row r) x (4 batches)
        float ax = 0.f, ay = 0.f, az = 0.f, aw = 0.f;
        const float4* hp = (const float4*)h_s + bg;   // h_s4[k][bg], stride 16
#pragma unroll 8
        for (int kk = 0; kk < 64; kk++) {
            float4 wv = wrow[kk];
            float4 h0 = hp[(kk * 4 + 0) * 16];
            float4 h1 = hp[(kk * 4 + 1) * 16];
            float4 h2 = hp[(kk * 4 + 2) * 16];
            float4 h3 = hp[(kk * 4 + 3) * 16];
            ax += wv.x * h0.x; ay += wv.x * h0.y; az += wv.x * h0.z; aw += wv.x * h0.w;
            ax += wv.y * h1.x; ay += wv.y * h1.y; az += wv.y * h1.z; aw += wv.y * h1.w;
            ax += wv.z * h2.x; ay += wv.z * h2.y; az += wv.z * h2.z; aw += wv.z * h2.w;
            ax += wv.w * h3.x; ay += wv.w * h3.y; az += wv.w * h3.z; aw += wv.w * h3.w;
        }
        a_s[r * 64 + (bg << 2) + 0] = ax + gin0;
        a_s[r * 64 + (bg << 2) + 1] = ay + gin1;
        a_s[r * 64 + (bg << 2) + 2] = az + gin2;
        a_s[r * 64 + (bg << 2) + 3] = aw + gin3;
        __syncthreads();

        // gate math + state update: thread = (unit uu, batch bb)
        float gi = a_s[(uu * 4 + 0) * 64 + bb];
        float gf = a_s[(uu * 4 + 1) * 64 + bb];
        float gc = a_s[(uu * 4 + 2) * 64 + bb];
        float go = a_s[(uu * 4 + 3) * 64 + bb];
        float c = sigf(gf) * c_s[(uu << 6) + bb] + sigf(gi) * tanhf(gc);
        float h = sigf(go) * tanhf(c);
        c_s[(uu << 6) + bb] = c;
        g_h[((((t + 1) & 1) * 2 + dir) << 14) + ((j0 + uu) << 6) + bb] = h;
        xT[(size_t)jrow * MROWS + (t << 6) + bb] = h;

        // grid-wide barrier (skip after last step)
        __threadfence();
        __syncthreads();
        if (t < T_SEQ - 1) {
            if (tid == 0) {
                unsigned prev = atomicAdd(&g_bar[t], 1u);
                if (prev < NBLK - 1) {
                    while (*(volatile unsigned*)&g_bar[t] < NBLK) __nanosleep(64);
                }
            }
            __syncthreads();
        }
    }
}

// ---------------- classifier ----------------
__global__ void k_clf(const int* __restrict__ tidx, const float* __restrict__ cw,
                      const float* __restrict__ cb, float* __restrict__ out) {
    __shared__ float red[128];
    int b = blockIdx.x;
    int col = tidx[b] * BATCH + b;
    float s = 0.f;
    for (int k = threadIdx.x; k < 512; k += 128)
        s += g_x2T[(size_t)k * MROWS + col] * cw[k];
    red[threadIdx.x] = s;
    __syncthreads();
    for (int off = 64; off > 0; off >>= 1) {
        if (threadIdx.x < off) red[threadIdx.x] += red[threadIdx.x + off];
        __syncthreads();
    }
    if (threadIdx.x == 0) out[b] = 1.f / (1.f + expf(-(red[0] + cb[0])));
}

// ---------------- host ----------------
extern "C" void kernel_launch(void* const* d_in, const int* in_sizes, int n_in,
                              void* d_out, int out_size) {
    const int*   inp  = (const int*)  d_in[0];
    const int*   tidx = (const int*)  d_in[1];
    const float* emb  = (const float*)d_in[2];
    const float* wih0 = (const float*)d_in[3];
    const float* whh0 = (const float*)d_in[4];
    const float* bih0 = (const float*)d_in[5];
    const float* bhh0 = (const float*)d_in[6];
    const float* wih1 = (const float*)d_in[7];
    const float* whh1 = (const float*)d_in[8];
    const float* bih1 = (const float*)d_in[9];
    const float* bhh1 = (const float*)d_in[10];
    const float* clfw = (const float*)d_in[11];
    const float* clfb = (const float*)d_in[12];
    float* out = (float*)d_out;

    const int SMEM = (16 * 260 + 256 * 64 + 16 * 64 + 4 * 64) * 4;  // 87296 B
    cudaFuncSetAttribute(k_lstm, cudaFuncAttributeMaxDynamicSharedMemorySize, SMEM);

    // layer 0
    k_padw<<<NGATE, 128>>>(wih0);
    k_embed<<<MROWS, 128>>>(inp, emb);
    k_gemm<0><<<dim3(32, 128), 256>>>(nullptr, bih0, bhh0);
    k_zero<<<256, 256>>>();
    k_lstm<<<NBLK, 256, SMEM>>>(whh0, 0);

    // layer 1
    k_gemm<1><<<dim3(32, 128), 256>>>(wih1, bih1, bhh1);
    k_zero<<<256, 256>>>();
    k_lstm<<<NBLK, 256, SMEM>>>(whh1, 1);

    // classifier
    k_clf<<<BATCH, 128>>>(tidx, clfw, clfb, out);
}

// round 4
// speedup vs baseline: 1.3000x; 1.3000x over previous
#include <cuda_runtime.h>
#include <math.h>
#include <stdint.h>

#define T_SEQ 256
#define BATCH 64
#define HID   256
#define NGATE 2048              // 2 dirs * 4H
#define MROWS (T_SEQ*BATCH)     // 16384
#define K0P   304               // padded input dim for layer 0 (300 -> 304), 19*16
#define NBLK  128               // persistent blocks in recurrent kernel

// ---------------- scratch (device globals; no allocation allowed) ----------------
__device__ float    g_x0[(size_t)MROWS * K0P];      // embedded input, padded
__device__ float    g_wpad0[NGATE * K0P];           // padded wih0
__device__ float    g_gates[(size_t)MROWS * NGATE]; // input-gate projections
__device__ float    g_x1[(size_t)MROWS * 512];      // layer-0 output, row-major [m][512]
__device__ float    g_x2T[(size_t)512 * MROWS];     // layer-1 output, feat-major [feat][m]
__device__ float    g_h[2 * 2 * HID * BATCH];       // double-buffered h: [buf][dir][j][b]
__device__ unsigned g_bar[T_SEQ];                   // per-step barrier counters

// ---------------- small kernels ----------------
__global__ void k_padw(const float* __restrict__ w) {
    int n = blockIdx.x;
    float* o = g_wpad0 + n * K0P;
    const float* s = w + n * 300;
    for (int k = threadIdx.x; k < K0P; k += blockDim.x)
        o[k] = (k < 300) ? s[k] : 0.f;
}

__global__ void k_embed(const int* __restrict__ inp, const float* __restrict__ emb) {
    int m = blockIdx.x;            // m = t*64 + b
    int t = m >> 6, b = m & 63;
    int idx = inp[b * T_SEQ + t];
    const float* e = emb + (size_t)idx * 300;
    float* o = g_x0 + (size_t)m * K0P;
    for (int k = threadIdx.x; k < K0P; k += blockDim.x)
        o[k] = (k < 300) ? e[k] : 0.f;
}

__global__ void k_zero() { g_bar[threadIdx.x] = 0u; }   // 256 threads, 1 block

// ---------------- tf32 tensor-core GEMM ----------------
// gates[m][n] = sum_k A[m][k]*W[n][k] + bi[n] + bh[n]
// LAYER 0: A = g_x0 [16384][304], W = g_wpad0 [2048][304], K=304
// LAYER 1: A = g_x1 [16384][512], W = wih1   [2048][512], K=512
__device__ __forceinline__ uint32_t f2tf(float x) {
    uint32_t r; asm("cvt.rna.tf32.f32 %0, %1;" : "=r"(r) : "f"(x)); return r;
}
__device__ __forceinline__ void mma8(float* c, const uint32_t* a, const uint32_t* b) {
    asm volatile("mma.sync.aligned.m16n8k8.row.col.f32.tf32.tf32.f32 "
                 "{%0,%1,%2,%3},{%4,%5,%6,%7},{%8,%9},{%0,%1,%2,%3};"
                 : "+f"(c[0]), "+f"(c[1]), "+f"(c[2]), "+f"(c[3])
                 : "r"(a[0]), "r"(a[1]), "r"(a[2]), "r"(a[3]),
                   "r"(b[0]), "r"(b[1]));
}

template<int LAYER>
__global__ __launch_bounds__(256) void k_gemm_tc(const float* __restrict__ Warg,
                                                 const float* __restrict__ bi,
                                                 const float* __restrict__ bh) {
    constexpr int K = LAYER ? 512 : K0P;
    constexpr int NST = K / 16;
    const float* A = LAYER ? g_x1 : g_x0;
    const float* W = LAYER ? Warg : g_wpad0;

    __shared__ uint32_t As[2][2048];   // [k8(2)][m_tile(8)][reg(4)][lane(32)]
    __shared__ uint32_t Bs[2][2048];   // [k8(2)][n_tile(16)][reg(2)][lane(32)]

    const int tid = threadIdx.x, lane = tid & 31, wid = tid >> 5;
    const int m0 = blockIdx.y << 7, n0 = blockIdx.x << 7;
    const int warp_m = wid & 1, warp_n = wid >> 1;   // warp tile 64(M) x 32(N)

    // staging setup: each thread moves 2 float4s of A and 2 of W per 16-k stage
    const float *agp[2], *wgp[2];
    int aoff[2], boff[2];
#pragma unroll
    for (int e = 0; e < 2; e++) {
        int q = tid * 2 + e, row = q >> 2, kq = q & 3;
        agp[e] = A + (size_t)(m0 + row) * K + (kq << 2);
        wgp[e] = W + (size_t)(n0 + row) * K + (kq << 2);
        int rt = row & 15, mt = row >> 4;
        aoff[e] = (((kq >> 1) * 8 + mt) * 4 + ((rt >> 3) & 1) + ((kq & 1) << 1)) * 32
                + ((rt & 7) << 2);
        boff[e] = (((kq >> 1) * 16 + (row >> 3)) * 2 + (kq & 1)) * 32
                + ((row & 7) << 2);
    }

    float c[4][4][4];
#pragma unroll
    for (int i = 0; i < 4; i++)
#pragma unroll
        for (int j = 0; j < 4; j++)
#pragma unroll
            for (int q = 0; q < 4; q++) c[i][j][q] = 0.f;

    // prologue: stage 0
#pragma unroll
    for (int e = 0; e < 2; e++) {
        float4 va = *(const float4*)agp[e];
        float4 vb = *(const float4*)wgp[e];
        *(uint4*)&As[0][aoff[e]] = make_uint4(f2tf(va.x), f2tf(va.y), f2tf(va.z), f2tf(va.w));
        *(uint4*)&Bs[0][boff[e]] = make_uint4(f2tf(vb.x), f2tf(vb.y), f2tf(vb.z), f2tf(vb.w));
    }
    __syncthreads();

    int buf = 0;
#pragma unroll 1
    for (int s = 0; s < NST; s++) {
        float4 va[2], vb[2];
        const bool more = (s + 1) < NST;
        if (more) {
#pragma unroll
            for (int e = 0; e < 2; e++) {
                va[e] = *(const float4*)(agp[e] + (s + 1) * 16);
                vb[e] = *(const float4*)(wgp[e] + (s + 1) * 16);
            }
        }
#pragma unroll
        for (int k8 = 0; k8 < 2; k8++) {
            uint32_t af[4][4], bf[4][2];
#pragma unroll
            for (int mt = 0; mt < 4; mt++) {
                int tb = (k8 * 8 + warp_m * 4 + mt) * 128 + lane;
#pragma unroll
                for (int r = 0; r < 4; r++) af[mt][r] = As[buf][tb + r * 32];
            }
#pragma unroll
            for (int nt = 0; nt < 4; nt++) {
                int tb = (k8 * 16 + warp_n * 4 + nt) * 64 + lane;
                bf[nt][0] = Bs[buf][tb];
                bf[nt][1] = Bs[buf][tb + 32];
            }
#pragma unroll
            for (int mt = 0; mt < 4; mt++)
#pragma unroll
                for (int nt = 0; nt < 4; nt++)
                    mma8(c[mt][nt], af[mt], bf[nt]);
        }
        if (more) {
            int nb = buf ^ 1;
#pragma unroll
            for (int e = 0; e < 2; e++) {
                *(uint4*)&As[nb][aoff[e]] =
                    make_uint4(f2tf(va[e].x), f2tf(va[e].y), f2tf(va[e].z), f2tf(va[e].w));
                *(uint4*)&Bs[nb][boff[e]] =
                    make_uint4(f2tf(vb[e].x), f2tf(vb[e].y), f2tf(vb[e].z), f2tf(vb[e].w));
            }
            __syncthreads();
            buf = nb;
        }
    }

    // epilogue: fused bias + store
    const int g = lane >> 2, lm = lane & 3;
#pragma unroll
    for (int nt = 0; nt < 4; nt++) {
        int n = n0 + warp_n * 32 + nt * 8 + lm * 2;
        float b0 = bi[n] + bh[n], b1 = bi[n + 1] + bh[n + 1];
#pragma unroll
        for (int mt = 0; mt < 4; mt++) {
            int r0 = m0 + warp_m * 64 + mt * 16 + g;
            *(float2*)&g_gates[(size_t)r0 * NGATE + n] =
                make_float2(c[mt][nt][0] + b0, c[mt][nt][1] + b1);
            *(float2*)&g_gates[(size_t)(r0 + 8) * NGATE + n] =
                make_float2(c[mt][nt][2] + b0, c[mt][nt][3] + b1);
        }
    }
}

// ---------------- recurrent scan (persistent, 128 blocks, release/acquire barrier) ----------------
__device__ __forceinline__ float sigf(float x) { return 1.f / (1.f + expf(-x)); }
__device__ __forceinline__ unsigned ld_acq(const unsigned* p) {
    unsigned v; asm volatile("ld.acquire.gpu.global.u32 %0, [%1];" : "=r"(v) : "l"(p)); return v;
}

__global__ __launch_bounds__(256, 1) void k_lstm(const float* __restrict__ whh, // [2048][256]
                                                 int layer) {
    extern __shared__ float sm[];
    float* w_s    = sm;                    // [16][260] (pad -> conflict-free)
    float* h_s    = sm + 16 * 260;         // [256][64]
    float* a_s    = h_s + 256 * 64;        // [16][64]
    float* c_s    = a_s + 16 * 64;         // [4][64]
    float* hstage = c_s + 256;             // [64][4] transpose staging (layer 0)

    const int tid = threadIdx.x;
    const int bid = blockIdx.x;
    const int dir = bid >> 6;              // 0/1
    const int j0  = (bid & 63) << 2;       // 4 hidden units per block

    // load this block's recurrent-weight slice once (16 gate rows x 256)
    for (int i = tid; i < 16 * 256; i += 256) {
        int r = i >> 8, k = i & 255;
        int gg = (r & 3) * HID + j0 + (r >> 2);  // gate-major (i,f,g,o)
        w_s[r * 260 + k] = whh[(size_t)(dir * 1024 + gg) * HID + k];
    }
    c_s[tid] = 0.f;
    {   // h(-1) = 0
        float4* h4 = (float4*)h_s;
#pragma unroll
        for (int i = 0; i < 16; i++) h4[tid + (i << 8)] = make_float4(0, 0, 0, 0);
    }
    __syncthreads();

    // dot-product thread mapping: warp = 4 gate-rows x 8 batch-groups
    const int w  = tid >> 5, l = tid & 31;
    const int r  = ((w & 3) << 2) | (l & 3);           // gate row 0..15
    const int bg = ((w >> 2) << 3) | (l >> 2);         // batch group 0..15
    const int gofs = dir * 1024 + (r & 3) * HID + j0 + (r >> 2);
    const float4* wrow = (const float4*)(w_s + r * 260);
    const int uu = tid >> 6, bb = tid & 63;

    for (int t = 0; t < T_SEQ; t++) {
        // prefetch precomputed input-gate terms (independent of barrier)
        const float* gb = g_gates + (size_t)((t << 6) + (bg << 2)) * NGATE + gofs;
        float gin0 = __ldg(gb + 0);
        float gin1 = __ldg(gb + NGATE);
        float gin2 = __ldg(gb + 2 * NGATE);
        float gin3 = __ldg(gb + 3 * NGATE);

        if (t > 0) {
            // wait for all blocks to publish h(t-1)
            const unsigned* bp = &g_bar[t - 1];
            while (ld_acq(bp) < NBLK) {}
            asm volatile("" ::: "memory");
            // load h(t-1): 64KB from L2 (.cg — L1 stale across SMs)
            const float4* hsrc = (const float4*)(g_h + ((((t - 1) & 1) * 2 + dir) << 14));
            float4* hd = (float4*)h_s;
#pragma unroll
            for (int i = 0; i < 16; i++)
                hd[tid + (i << 8)] = __ldcg(&hsrc[tid + (i << 8)]);
        }
        __syncthreads();

        // 256-long dot for (gate row r) x (4 batches)
        float ax = 0.f, ay = 0.f, az = 0.f, aw = 0.f;
        const float4* hp = (const float4*)h_s + bg;
#pragma unroll 8
        for (int kk = 0; kk < 64; kk++) {
            float4 wv = wrow[kk];
            float4 h0 = hp[(kk * 4 + 0) * 16];
            float4 h1 = hp[(kk * 4 + 1) * 16];
            float4 h2 = hp[(kk * 4 + 2) * 16];
            float4 h3 = hp[(kk * 4 + 3) * 16];
            ax += wv.x * h0.x; ay += wv.x * h0.y; az += wv.x * h0.z; aw += wv.x * h0.w;
            ax += wv.y * h1.x; ay += wv.y * h1.y; az += wv.y * h1.z; aw += wv.y * h1.w;
            ax += wv.z * h2.x; ay += wv.z * h2.y; az += wv.z * h2.z; aw += wv.z * h2.w;
            ax += wv.w * h3.x; ay += wv.w * h3.y; az += wv.w * h3.z; aw += wv.w * h3.w;
        }
        a_s[r * 64 + (bg << 2) + 0] = ax + gin0;
        a_s[r * 64 + (bg << 2) + 1] = ay + gin1;
        a_s[r * 64 + (bg << 2) + 2] = az + gin2;
        a_s[r * 64 + (bg << 2) + 3] = aw + gin3;
        __syncthreads();

        // gate math + state update: thread = (unit uu, batch bb)
        float gi = a_s[(uu * 4 + 0) * 64 + bb];
        float gf = a_s[(uu * 4 + 1) * 64 + bb];
        float gc = a_s[(uu * 4 + 2) * 64 + bb];
        float go = a_s[(uu * 4 + 3) * 64 + bb];
        float cc = sigf(gf) * c_s[(uu << 6) + bb] + sigf(gi) * tanhf(gc);
        float hh = sigf(go) * tanhf(cc);
        c_s[(uu << 6) + bb] = cc;
        g_h[(((t & 1) * 2 + dir) << 14) + ((j0 + uu) << 6) + bb] = hh;
        if (layer == 0) {
            hstage[bb * 4 + uu] = hh;                       // transpose stage
        } else {
            g_x2T[(size_t)(dir * HID + j0 + uu) * MROWS + (t << 6) + bb] = hh;
        }
        __syncthreads();   // h stores done block-wide (also covers hstage)
        if (tid == 0 && t < T_SEQ - 1)
            asm volatile("red.release.gpu.global.add.u32 [%0], 1;"
                         :: "l"(&g_bar[t]) : "memory");
        if (layer == 0 && tid < 64) {
            float4 v = *(float4*)&hstage[tid * 4];
            *(float4*)&g_x1[(size_t)((t << 6) + tid) * 512 + (dir << 8) + j0] = v;
        }
    }
}

// ---------------- classifier ----------------
__global__ void k_clf(const int* __restrict__ tidx, const float* __restrict__ cw,
                      const float* __restrict__ cb, float* __restrict__ out) {
    __shared__ float red[128];
    int b = blockIdx.x;
    int col = tidx[b] * BATCH + b;
    float s = 0.f;
    for (int k = threadIdx.x; k < 512; k += 128)
        s += g_x2T[(size_t)k * MROWS + col] * cw[k];
    red[threadIdx.x] = s;
    __syncthreads();
    for (int off = 64; off > 0; off >>= 1) {
        if (threadIdx.x < off) red[threadIdx.x] += red[threadIdx.x + off];
        __syncthreads();
    }
    if (threadIdx.x == 0) out[b] = 1.f / (1.f + expf(-(red[0] + cb[0])));
}

// ---------------- host ----------------
extern "C" void kernel_launch(void* const* d_in, const int* in_sizes, int n_in,
                              void* d_out, int out_size) {
    const int*   inp  = (const int*)  d_in[0];
    const int*   tidx = (const int*)  d_in[1];
    const float* emb  = (const float*)d_in[2];
    const float* wih0 = (const float*)d_in[3];
    const float* whh0 = (const float*)d_in[4];
    const float* bih0 = (const float*)d_in[5];
    const float* bhh0 = (const float*)d_in[6];
    const float* wih1 = (const float*)d_in[7];
    const float* whh1 = (const float*)d_in[8];
    const float* bih1 = (const float*)d_in[9];
    const float* bhh1 = (const float*)d_in[10];
    const float* clfw = (const float*)d_in[11];
    const float* clfb = (const float*)d_in[12];
    float* out = (float*)d_out;

    const int SMEM = (16 * 260 + 256 * 64 + 16 * 64 + 256 + 256) * 4;  // 88320 B
    cudaFuncSetAttribute(k_lstm, cudaFuncAttributeMaxDynamicSharedMemorySize, SMEM);

    // layer 0
    k_padw<<<NGATE, 128>>>(wih0);
    k_embed<<<MROWS, 128>>>(inp, emb);
    k_gemm_tc<0><<<dim3(16, 128), 256>>>(nullptr, bih0, bhh0);
    k_zero<<<1, 256>>>();
    k_lstm<<<NBLK, 256, SMEM>>>(whh0, 0);

    // layer 1
    k_gemm_tc<1><<<dim3(16, 128), 256>>>(wih1, bih1, bhh1);
    k_zero<<<1, 256>>>();
    k_lstm<<<NBLK, 256, SMEM>>>(whh1, 1);

    // classifier
    k_clf<<<BATCH, 128>>>(tidx, clfw, clfb, out);
}

// round 5
// speedup vs baseline: 1.7601x; 1.3539x over previous
#include <cuda_runtime.h>
#include <math.h>
#include <stdint.h>

#define T_SEQ 256
#define BATCH 64
#define HID   256
#define NGATE 2048              // 2 dirs * 4H
#define MROWS (T_SEQ*BATCH)     // 16384
#define K0P   304               // padded input dim for layer 0 (300 -> 304)
#define NBLK  64                // persistent blocks in recurrent kernel

// ---------------- scratch (device globals; no allocation allowed) ----------------
__device__ float    g_x0[(size_t)MROWS * K0P];      // embedded input, padded
__device__ float    g_wpad0[NGATE * K0P];           // padded wih0
__device__ float    g_gates[(size_t)MROWS * NGATE]; // input-gate projections
__device__ float    g_x1[(size_t)MROWS * 512];      // layer-0 output, row-major [m][512]
__device__ float    g_x2T[(size_t)512 * MROWS];     // layer-1 output, feat-major [feat][m]
__device__ float    g_h[2 * 2 * HID * BATCH];       // double-buffered h, fragment layout
__device__ unsigned g_bar[T_SEQ];                   // per-step barrier counters

// ---------------- small kernels ----------------
__global__ void k_padw(const float* __restrict__ w) {
    int n = blockIdx.x;
    float* o = g_wpad0 + n * K0P;
    const float* s = w + n * 300;
    for (int k = threadIdx.x; k < K0P; k += blockDim.x)
        o[k] = (k < 300) ? s[k] : 0.f;
}

__global__ void k_embed(const int* __restrict__ inp, const float* __restrict__ emb) {
    int m = blockIdx.x;            // m = t*64 + b
    int t = m >> 6, b = m & 63;
    int idx = inp[b * T_SEQ + t];
    const float* e = emb + (size_t)idx * 300;
    float* o = g_x0 + (size_t)m * K0P;
    for (int k = threadIdx.x; k < K0P; k += blockDim.x)
        o[k] = (k < 300) ? e[k] : 0.f;
}

// ---------------- tf32 helpers ----------------
__device__ __forceinline__ uint32_t f2tf(float x) {
    uint32_t r; asm("cvt.rna.tf32.f32 %0, %1;" : "=r"(r) : "f"(x)); return r;
}
__device__ __forceinline__ void mma8(float* c, const uint32_t* a, const uint32_t* b) {
    asm volatile("mma.sync.aligned.m16n8k8.row.col.f32.tf32.tf32.f32 "
                 "{%0,%1,%2,%3},{%4,%5,%6,%7},{%8,%9},{%0,%1,%2,%3};"
                 : "+f"(c[0]), "+f"(c[1]), "+f"(c[2]), "+f"(c[3])
                 : "r"(a[0]), "r"(a[1]), "r"(a[2]), "r"(a[3]),
                   "r"(b[0]), "r"(b[1]));
}

// ---------------- tf32 tensor-core GEMM (input projections) ----------------
// gates[m][n] = sum_k A[m][k]*W[n][k] + bi[n] + bh[n]
template<int LAYER>
__global__ __launch_bounds__(256) void k_gemm_tc(const float* __restrict__ Warg,
                                                 const float* __restrict__ bi,
                                                 const float* __restrict__ bh) {
    constexpr int K = LAYER ? 512 : K0P;
    constexpr int NST = K / 16;
    const float* A = LAYER ? g_x1 : g_x0;
    const float* W = LAYER ? Warg : g_wpad0;

    // fold-in: zero the scan barrier for the following k_lstm launch
    if (blockIdx.x == 0 && blockIdx.y == 0 && threadIdx.x < T_SEQ)
        g_bar[threadIdx.x] = 0u;

    __shared__ uint32_t As[2][2048];
    __shared__ uint32_t Bs[2][2048];

    const int tid = threadIdx.x, lane = tid & 31, wid = tid >> 5;
    const int m0 = blockIdx.y << 7, n0 = blockIdx.x << 7;
    const int warp_m = wid & 1, warp_n = wid >> 1;

    const float *agp[2], *wgp[2];
    int aoff[2], boff[2];
#pragma unroll
    for (int e = 0; e < 2; e++) {
        int q = tid * 2 + e, row = q >> 2, kq = q & 3;
        agp[e] = A + (size_t)(m0 + row) * K + (kq << 2);
        wgp[e] = W + (size_t)(n0 + row) * K + (kq << 2);
        int rt = row & 15, mt = row >> 4;
        aoff[e] = (((kq >> 1) * 8 + mt) * 4 + ((rt >> 3) & 1) + ((kq & 1) << 1)) * 32
                + ((rt & 7) << 2);
        boff[e] = (((kq >> 1) * 16 + (row >> 3)) * 2 + (kq & 1)) * 32
                + ((row & 7) << 2);
    }

    float c[4][4][4];
#pragma unroll
    for (int i = 0; i < 4; i++)
#pragma unroll
        for (int j = 0; j < 4; j++)
#pragma unroll
            for (int q = 0; q < 4; q++) c[i][j][q] = 0.f;

#pragma unroll
    for (int e = 0; e < 2; e++) {
        float4 va = *(const float4*)agp[e];
        float4 vb = *(const float4*)wgp[e];
        *(uint4*)&As[0][aoff[e]] = make_uint4(f2tf(va.x), f2tf(va.y), f2tf(va.z), f2tf(va.w));
        *(uint4*)&Bs[0][boff[e]] = make_uint4(f2tf(vb.x), f2tf(vb.y), f2tf(vb.z), f2tf(vb.w));
    }
    __syncthreads();

    int buf = 0;
#pragma unroll 1
    for (int s = 0; s < NST; s++) {
        float4 va[2], vb[2];
        const bool more = (s + 1) < NST;
        if (more) {
#pragma unroll
            for (int e = 0; e < 2; e++) {
                va[e] = *(const float4*)(agp[e] + (s + 1) * 16);
                vb[e] = *(const float4*)(wgp[e] + (s + 1) * 16);
            }
        }
#pragma unroll
        for (int k8 = 0; k8 < 2; k8++) {
            uint32_t af[4][4], bf[4][2];
#pragma unroll
            for (int mt = 0; mt < 4; mt++) {
                int tb = (k8 * 8 + warp_m * 4 + mt) * 128 + lane;
#pragma unroll
                for (int r = 0; r < 4; r++) af[mt][r] = As[buf][tb + r * 32];
            }
#pragma unroll
            for (int nt = 0; nt < 4; nt++) {
                int tb = (k8 * 16 + warp_n * 4 + nt) * 64 + lane;
                bf[nt][0] = Bs[buf][tb];
                bf[nt][1] = Bs[buf][tb + 32];
            }
#pragma unroll
            for (int mt = 0; mt < 4; mt++)
#pragma unroll
                for (int nt = 0; nt < 4; nt++)
                    mma8(c[mt][nt], af[mt], bf[nt]);
        }
        if (more) {
            int nb = buf ^ 1;
#pragma unroll
            for (int e = 0; e < 2; e++) {
                *(uint4*)&As[nb][aoff[e]] =
                    make_uint4(f2tf(va[e].x), f2tf(va[e].y), f2tf(va[e].z), f2tf(va[e].w));
                *(uint4*)&Bs[nb][boff[e]] =
                    make_uint4(f2tf(vb[e].x), f2tf(vb[e].y), f2tf(vb[e].z), f2tf(vb[e].w));
            }
            __syncthreads();
            buf = nb;
        }
    }

    const int g = lane >> 2, lm = lane & 3;
#pragma unroll
    for (int nt = 0; nt < 4; nt++) {
        int n = n0 + warp_n * 32 + nt * 8 + lm * 2;
        float b0 = bi[n] + bh[n], b1 = bi[n + 1] + bh[n + 1];
#pragma unroll
        for (int mt = 0; mt < 4; mt++) {
            int r0 = m0 + warp_m * 64 + mt * 16 + g;
            *(float2*)&g_gates[(size_t)r0 * NGATE + n] =
                make_float2(c[mt][nt][0] + b0, c[mt][nt][1] + b1);
            *(float2*)&g_gates[(size_t)(r0 + 8) * NGATE + n] =
                make_float2(c[mt][nt][2] + b0, c[mt][nt][3] + b1);
        }
    }
}

// ---------------- recurrent scan: tensor-core persistent kernel ----------------
// 64 blocks (32 per dir). Block owns 8 hidden units (= 32 gate rows), all 64 batches.
// W^T held permanently in registers as tf32 B fragments. k split 4-ways over warps.
//
// h global layout (per buf, per dir; 16384 floats), fragment-native:
//   addr(k,b) = ((k>>3)*4 + (b>>4))*128 + (b&7)*16 + (k&3)*4 + ((k&4)>>1 | (b&8)>>3)
// so one A-fragment (a0..a3) for a (16-batch x 8-k) tile = one coalesced LDG.128.
__device__ __forceinline__ float sigf(float x) { return 1.f / (1.f + expf(-x)); }
__device__ __forceinline__ unsigned ld_acq(const unsigned* p) {
    unsigned v; asm volatile("ld.acquire.gpu.global.u32 %0, [%1];" : "=r"(v) : "l"(p)); return v;
}
__device__ __forceinline__ float4 ldcg4(const float4* p) {
    float4 v;
    asm volatile("ld.global.cg.v4.f32 {%0,%1,%2,%3}, [%4];"
                 : "=f"(v.x), "=f"(v.y), "=f"(v.z), "=f"(v.w) : "l"(p));
    return v;
}

__global__ __launch_bounds__(256, 1) void k_lstm(const float* __restrict__ whh, // [2048][256]
                                                 int layer) {
    __shared__ float psum[4 * 32 * 68];   // [kq][n][b], row stride 68 (conflict-free)
    __shared__ float hsm[BATCH * 8];      // [b][u]

    const int tid = threadIdx.x, lane = tid & 31, wid = tid >> 5;
    const int bid = blockIdx.x;
    const int dir = bid >> 5;             // 0/1
    const int j0  = (bid & 31) << 3;      // 8 hidden units per block
    const int mh  = wid >> 2;             // batch half 0/1
    const int kq  = wid & 3;              // k quarter 0..3

    // --- persistent B fragments: W^T slice, tf32, 64 regs ---
    uint32_t bfr[4][8][2];
    {
        const int nr = lane >> 2, kl = lane & 3;
#pragma unroll
        for (int nt = 0; nt < 4; nt++) {
            int nn = nt * 8 + nr;                       // n index 0..31
            int row = dir * 1024 + (nn & 3) * 256 + j0 + (nn >> 2);
            const float* wr = whh + (size_t)row * 256 + kq * 64 + kl;
#pragma unroll
            for (int kt = 0; kt < 8; kt++) {
                bfr[nt][kt][0] = f2tf(wr[kt * 8]);
                bfr[nt][kt][1] = f2tf(wr[kt * 8 + 4]);
            }
        }
    }

    // gate-math mapping: thread -> (u4, b), handles units u4 and u4+4
    const int u4 = tid >> 6, b = tid & 63;
    float cst0 = 0.f, cst1 = 0.f;          // cell states for the 2 (u,b) pairs

    for (int t = 0; t < T_SEQ; t++) {
        // prefetch input-gate terms (DRAM; independent of barrier)
        const float* grow = g_gates + (size_t)((t << 6) + b) * NGATE + dir * 1024 + j0 + u4;
        float gin[2][4];
#pragma unroll
        for (int p = 0; p < 2; p++)
#pragma unroll
            for (int g = 0; g < 4; g++)
                gin[p][g] = __ldg(grow + g * 256 + 4 * p);

        if (t > 0) {
            // wait for all blocks to publish h(t-1)
            const unsigned* bp = &g_bar[t - 1];
            while (ld_acq(bp) < NBLK) {}
            asm volatile("" ::: "memory");

            // load A fragments: 16 coalesced LDG.128 per warp (64KB/block from L2)
            const float4* hb = (const float4*)(g_h + ((((t - 1) & 1) * 2 + dir) << 14));
            float4 aq[2][8];
#pragma unroll
            for (int kt = 0; kt < 8; kt++)
#pragma unroll
                for (int mt = 0; mt < 2; mt++)
                    aq[mt][kt] = ldcg4(hb + ((kq * 8 + kt) * 4 + mh * 2 + mt) * 32 + lane);

            float acc[2][4][4];
#pragma unroll
            for (int i = 0; i < 2; i++)
#pragma unroll
                for (int j = 0; j < 4; j++)
#pragma unroll
                    for (int q = 0; q < 4; q++) acc[i][j][q] = 0.f;

#pragma unroll
            for (int kt = 0; kt < 8; kt++)
#pragma unroll
                for (int mt = 0; mt < 2; mt++) {
                    uint32_t au[4] = { f2tf(aq[mt][kt].x), f2tf(aq[mt][kt].y),
                                       f2tf(aq[mt][kt].z), f2tf(aq[mt][kt].w) };
#pragma unroll
                    for (int nt = 0; nt < 4; nt++)
                        mma8(acc[mt][nt], au, bfr[nt][kt]);
                }

            // store partials (conflict-free: bank = 4*n + b perm)
#pragma unroll
            for (int mt = 0; mt < 2; mt++)
#pragma unroll
                for (int nt = 0; nt < 4; nt++) {
                    int n0 = nt * 8 + (lane & 3) * 2;
                    int bb = mh * 32 + mt * 16 + (lane >> 2);
                    float* pp = psum + (kq * 32 + n0) * 68 + bb;
                    pp[0]      = acc[mt][nt][0];
                    pp[68]     = acc[mt][nt][1];
                    pp[8]      = acc[mt][nt][2];
                    pp[68 + 8] = acc[mt][nt][3];
                }
        }
        __syncthreads();

        // gate math: reduce 4 k-partials + gin, activations, cell update
#pragma unroll
        for (int p = 0; p < 2; p++) {
            float v0 = gin[p][0], v1 = gin[p][1], v2 = gin[p][2], v3 = gin[p][3];
            if (t > 0) {
                int n = (u4 + 4 * p) * 4;
#pragma unroll
                for (int q = 0; q < 4; q++) {
                    const float* pp = psum + (q * 32 + n) * 68 + b;
                    v0 += pp[0]; v1 += pp[68]; v2 += pp[2 * 68]; v3 += pp[3 * 68];
                }
            }
            float ci = sigf(v0), cf = sigf(v1), cg = tanhf(v2), co = sigf(v3);
            float cprev = p ? cst1 : cst0;
            float cc = cf * cprev + ci * cg;
            float hh = co * tanhf(cc);
            if (p) cst1 = cc; else cst0 = cc;
            hsm[b * 8 + u4 + 4 * p] = hh;
            if (layer)
                g_x2T[(size_t)(dir * 256 + j0 + u4 + 4 * p) * MROWS + (t << 6) + b] = hh;
        }
        __syncthreads();

        // publish h(t) in fragment layout (coalesced STG.128 via smem transpose)
        if (tid < 128) {
            int bq = tid >> 5, r = (tid >> 2) & 7, kl = tid & 3;
            int s0 = (bq * 16 + r) * 8 + kl;
            float4 v = make_float4(hsm[s0], hsm[s0 + 64], hsm[s0 + 4], hsm[s0 + 68]);
            float* hbo = g_h + (((t & 1) * 2 + dir) << 14);
            *(float4*)&hbo[(((j0 >> 3) * 4 + bq) << 7) + r * 16 + kl * 4] = v;
            if (layer == 0) {
                int b2 = tid >> 1, half = tid & 1;
                float4 w = *(float4*)&hsm[b2 * 8 + half * 4];
                *(float4*)&g_x1[(size_t)((t << 6) + b2) * 512 + dir * 256 + j0 + half * 4] = w;
            }
        }
        __syncthreads();
        if (tid == 0 && t < T_SEQ - 1)
            asm volatile("red.release.gpu.global.add.u32 [%0], 1;"
                         :: "l"(&g_bar[t]) : "memory");
    }
}

// ---------------- classifier ----------------
__global__ void k_clf(const int* __restrict__ tidx, const float* __restrict__ cw,
                      const float* __restrict__ cb, float* __restrict__ out) {
    __shared__ float red[128];
    int b = blockIdx.x;
    int col = tidx[b] * BATCH + b;
    float s = 0.f;
    for (int k = threadIdx.x; k < 512; k += 128)
        s += g_x2T[(size_t)k * MROWS + col] * cw[k];
    red[threadIdx.x] = s;
    __syncthreads();
    for (int off = 64; off > 0; off >>= 1) {
        if (threadIdx.x < off) red[threadIdx.x] += red[threadIdx.x + off];
        __syncthreads();
    }
    if (threadIdx.x == 0) out[b] = 1.f / (1.f + expf(-(red[0] + cb[0])));
}

// ---------------- host ----------------
extern "C" void kernel_launch(void* const* d_in, const int* in_sizes, int n_in,
                              void* d_out, int out_size) {
    const int*   inp  = (const int*)  d_in[0];
    const int*   tidx = (const int*)  d_in[1];
    const float* emb  = (const float*)d_in[2];
    const float* wih0 = (const float*)d_in[3];
    const float* whh0 = (const float*)d_in[4];
    const float* bih0 = (const float*)d_in[5];
    const float* bhh0 = (const float*)d_in[6];
    const float* wih1 = (const float*)d_in[7];
    const float* whh1 = (const float*)d_in[8];
    const float* bih1 = (const float*)d_in[9];
    const float* bhh1 = (const float*)d_in[10];
    const float* clfw = (const float*)d_in[11];
    const float* clfb = (const float*)d_in[12];
    float* out = (float*)d_out;

    // layer 0
    k_padw<<<NGATE, 128>>>(wih0);
    k_embed<<<MROWS, 128>>>(inp, emb);
    k_gemm_tc<0><<<dim3(16, 128), 256>>>(nullptr, bih0, bhh0);   // also zeros g_bar
    k_lstm<<<NBLK, 256>>>(whh0, 0);

    // layer 1
    k_gemm_tc<1><<<dim3(16, 128), 256>>>(wih1, bih1, bhh1);      // also zeros g_bar
    k_lstm<<<NBLK, 256>>>(whh1, 1);

    // classifier
    k_clf<<<BATCH, 128>>>(tidx, clfw, clfb, out);
}

// round 6
// speedup vs baseline: 2.5322x; 1.4387x over previous
#include <cuda_runtime.h>
#include <math.h>
#include <stdint.h>

#define T_SEQ 256
#define BATCH 64
#define HID   256
#define NGATE 2048              // 2 dirs * 4H
#define MROWS (T_SEQ*BATCH)     // 16384
#define K0P   304               // padded input dim for layer 0 (300 -> 304)
#define NBLK  64                // persistent blocks in recurrent kernel

// ---------------- scratch (device globals; no allocation allowed) ----------------
__device__ float    g_x0[(size_t)MROWS * K0P];      // embedded input, padded
__device__ float    g_wpad0[NGATE * K0P];           // padded wih0
// gates layout: [blk(64)][t(256)][b(64)][g*8+u(32)]  (blk = dir*32 + j0/8)
__device__ float    g_gates[(size_t)MROWS * NGATE];
__device__ float    g_x1[(size_t)MROWS * 512];      // layer-0 output, row-major [m][512]
__device__ float    g_x2T[(size_t)512 * MROWS];     // layer-1 output, feat-major [feat][m]
__device__ uint32_t g_hb[2 * 2 * 8192];             // double-buffered h, bf16 frag layout
__device__ unsigned g_bar[T_SEQ];                   // per-step barrier counters

// ---------------- small kernels ----------------
__global__ void k_padw(const float* __restrict__ w) {
    int n = blockIdx.x;
    float* o = g_wpad0 + n * K0P;
    const float* s = w + n * 300;
    for (int k = threadIdx.x; k < K0P; k += blockDim.x)
        o[k] = (k < 300) ? s[k] : 0.f;
}

__global__ void k_embed(const int* __restrict__ inp, const float* __restrict__ emb) {
    int m = blockIdx.x;            // m = t*64 + b
    int t = m >> 6, b = m & 63;
    int idx = inp[b * T_SEQ + t];
    const float* e = emb + (size_t)idx * 300;
    float* o = g_x0 + (size_t)m * K0P;
    for (int k = threadIdx.x; k < K0P; k += blockDim.x)
        o[k] = (k < 300) ? e[k] : 0.f;
}

// ---------------- numeric helpers ----------------
__device__ __forceinline__ uint32_t f2tf(float x) {
    uint32_t r; asm("cvt.rna.tf32.f32 %0, %1;" : "=r"(r) : "f"(x)); return r;
}
__device__ __forceinline__ uint32_t pk_bf2(float lo, float hi) {   // .lo=lo, .hi=hi
    uint32_t r; asm("cvt.rn.bf16x2.f32 %0, %1, %2;" : "=r"(r) : "f"(hi), "f"(lo)); return r;
}
__device__ __forceinline__ void mma8(float* c, const uint32_t* a, const uint32_t* b) {
    asm volatile("mma.sync.aligned.m16n8k8.row.col.f32.tf32.tf32.f32 "
                 "{%0,%1,%2,%3},{%4,%5,%6,%7},{%8,%9},{%0,%1,%2,%3};"
                 : "+f"(c[0]), "+f"(c[1]), "+f"(c[2]), "+f"(c[3])
                 : "r"(a[0]), "r"(a[1]), "r"(a[2]), "r"(a[3]),
                   "r"(b[0]), "r"(b[1]));
}
__device__ __forceinline__ void mma16bf(float* c, const uint32_t* a, const uint32_t* b) {
    asm volatile("mma.sync.aligned.m16n8k16.row.col.f32.bf16.bf16.f32 "
                 "{%0,%1,%2,%3},{%4,%5,%6,%7},{%8,%9},{%0,%1,%2,%3};"
                 : "+f"(c[0]), "+f"(c[1]), "+f"(c[2]), "+f"(c[3])
                 : "r"(a[0]), "r"(a[1]), "r"(a[2]), "r"(a[3]),
                   "r"(b[0]), "r"(b[1]));
}
__device__ __forceinline__ float tanha(float x) {
    float y; asm("tanh.approx.f32 %0, %1;" : "=f"(y) : "f"(x)); return y;
}
__device__ __forceinline__ float siga(float x) { return fmaf(0.5f, tanha(0.5f * x), 0.5f); }
__device__ __forceinline__ unsigned ld_acq(const unsigned* p) {
    unsigned v; asm volatile("ld.acquire.gpu.global.u32 %0, [%1];" : "=r"(v) : "l"(p)); return v;
}
__device__ __forceinline__ uint4 ldcg_u4(const uint4* p) {
    uint4 v;
    asm volatile("ld.global.cg.v4.u32 {%0,%1,%2,%3}, [%4];"
                 : "=r"(v.x), "=r"(v.y), "=r"(v.z), "=r"(v.w) : "l"(p));
    return v;
}

// ---------------- tf32 tensor-core GEMM (input projections) ----------------
// gates[...] = sum_k A[m][k]*W[n][k] + bi[n] + bh[n], written in scan-friendly layout.
template<int LAYER>
__global__ __launch_bounds__(256) void k_gemm_tc(const float* __restrict__ Warg,
                                                 const float* __restrict__ bi,
                                                 const float* __restrict__ bh) {
    constexpr int K = LAYER ? 512 : K0P;
    constexpr int NST = K / 16;
    const float* A = LAYER ? g_x1 : g_x0;
    const float* W = LAYER ? Warg : g_wpad0;

    // fold-in: zero the scan barrier for the following k_lstm launch
    if (blockIdx.x == 0 && blockIdx.y == 0 && threadIdx.x < T_SEQ)
        g_bar[threadIdx.x] = 0u;

    __shared__ uint32_t As[2][2048];
    __shared__ uint32_t Bs[2][2048];

    const int tid = threadIdx.x, lane = tid & 31, wid = tid >> 5;
    const int m0 = blockIdx.y << 7, n0 = blockIdx.x << 7;
    const int warp_m = wid & 1, warp_n = wid >> 1;

    const float *agp[2], *wgp[2];
    int aoff[2], boff[2];
#pragma unroll
    for (int e = 0; e < 2; e++) {
        int q = tid * 2 + e, row = q >> 2, kq = q & 3;
        agp[e] = A + (size_t)(m0 + row) * K + (kq << 2);
        wgp[e] = W + (size_t)(n0 + row) * K + (kq << 2);
        int rt = row & 15, mt = row >> 4;
        aoff[e] = (((kq >> 1) * 8 + mt) * 4 + ((rt >> 3) & 1) + ((kq & 1) << 1)) * 32
                + ((rt & 7) << 2);
        boff[e] = (((kq >> 1) * 16 + (row >> 3)) * 2 + (kq & 1)) * 32
                + ((row & 7) << 2);
    }

    float c[4][4][4];
#pragma unroll
    for (int i = 0; i < 4; i++)
#pragma unroll
        for (int j = 0; j < 4; j++)
#pragma unroll
            for (int q = 0; q < 4; q++) c[i][j][q] = 0.f;

#pragma unroll
    for (int e = 0; e < 2; e++) {
        float4 va = *(const float4*)agp[e];
        float4 vb = *(const float4*)wgp[e];
        *(uint4*)&As[0][aoff[e]] = make_uint4(f2tf(va.x), f2tf(va.y), f2tf(va.z), f2tf(va.w));
        *(uint4*)&Bs[0][boff[e]] = make_uint4(f2tf(vb.x), f2tf(vb.y), f2tf(vb.z), f2tf(vb.w));
    }
    __syncthreads();

    int buf = 0;
#pragma unroll 1
    for (int s = 0; s < NST; s++) {
        float4 va[2], vb[2];
        const bool more = (s + 1) < NST;
        if (more) {
#pragma unroll
            for (int e = 0; e < 2; e++) {
                va[e] = *(const float4*)(agp[e] + (s + 1) * 16);
                vb[e] = *(const float4*)(wgp[e] + (s + 1) * 16);
            }
        }
#pragma unroll
        for (int k8 = 0; k8 < 2; k8++) {
            uint32_t af[4][4], bf[4][2];
#pragma unroll
            for (int mt = 0; mt < 4; mt++) {
                int tb = (k8 * 8 + warp_m * 4 + mt) * 128 + lane;
#pragma unroll
                for (int r = 0; r < 4; r++) af[mt][r] = As[buf][tb + r * 32];
            }
#pragma unroll
            for (int nt = 0; nt < 4; nt++) {
                int tb = (k8 * 16 + warp_n * 4 + nt) * 64 + lane;
                bf[nt][0] = Bs[buf][tb];
                bf[nt][1] = Bs[buf][tb + 32];
            }
#pragma unroll
            for (int mt = 0; mt < 4; mt++)
#pragma unroll
                for (int nt = 0; nt < 4; nt++)
                    mma8(c[mt][nt], af[mt], bf[nt]);
        }
        if (more) {
            int nb = buf ^ 1;
#pragma unroll
            for (int e = 0; e < 2; e++) {
                *(uint4*)&As[nb][aoff[e]] =
                    make_uint4(f2tf(va[e].x), f2tf(va[e].y), f2tf(va[e].z), f2tf(va[e].w));
                *(uint4*)&Bs[nb][boff[e]] =
                    make_uint4(f2tf(vb[e].x), f2tf(vb[e].y), f2tf(vb[e].z), f2tf(vb[e].w));
            }
            __syncthreads();
            buf = nb;
        }
    }

    // epilogue: fused bias + store to scan-friendly layout
    const int gq = lane >> 2, lm = lane & 3;
#pragma unroll
    for (int nt = 0; nt < 4; nt++) {
        int n = n0 + warp_n * 32 + nt * 8 + lm * 2;
        int dir = n >> 10, g = (n >> 8) & 3, j = n & 255;
        int blk = dir * 32 + (j >> 3), u = j & 7;
        float b0 = bi[n] + bh[n], b1 = bi[n + 1] + bh[n + 1];
#pragma unroll
        for (int mt = 0; mt < 4; mt++) {
            int r0 = m0 + warp_m * 64 + mt * 16 + gq;
            int t = r0 >> 6, bb = r0 & 63;
            size_t base = ((size_t)(blk * 256 + t) * 64);
            *(float2*)&g_gates[(base + bb) * 32 + g * 8 + u] =
                make_float2(c[mt][nt][0] + b0, c[mt][nt][1] + b1);
            *(float2*)&g_gates[(base + bb + 8) * 32 + g * 8 + u] =
                make_float2(c[mt][nt][2] + b0, c[mt][nt][3] + b1);
        }
    }
}

// ---------------- recurrent scan: bf16 tensor-core persistent kernel ----------------
// 64 blocks (32/dir). Block owns 8 hidden units (32 gate rows) x 64 batches.
// W^T held in registers as bf16 B-fragments; h exchanged in bf16 fragment-native
// global layout: per (buf,dir), 64 tiles of 16b x 16k; tile = 512B; within tile,
// lane l holds uint4 at tile*128 + l*4 u32 = A-fragment regs a0..a3 for m16n8k16.
__global__ __launch_bounds__(256, 1) void k_lstm(const float* __restrict__ whh, // [2048][256]
                                                 int layer) {
    __shared__ float gsm[64 * 33];        // staged input-gate terms, pad-33 conflict-free
    __shared__ float psum[4 * 32 * 68];   // k-split partials [kq][n][b]
    __shared__ float hsm[64 * 9];         // h(t) staging [b][u], pad-9

    const int tid = threadIdx.x, lane = tid & 31, wid = tid >> 5;
    const int bid = blockIdx.x;
    const int dir = bid >> 5;             // 0/1
    const int j0  = (bid & 31) << 3;      // 8 hidden units per block
    const int mh  = wid >> 2;             // batch half 0/1
    const int kq  = wid & 3;              // k quarter 0..3

    // --- persistent B fragments: W^T slice, bf16, 32 regs ---
    uint32_t bfr[4][4][2];
    {
        const int nr = lane >> 2, kl2 = (lane & 3) * 2;
#pragma unroll
        for (int nt = 0; nt < 4; nt++) {
            int nn = nt * 8 + nr;                       // gate-row 0..31
            int row = dir * 1024 + (nn & 3) * 256 + j0 + (nn >> 2);
            const float* wr = whh + (size_t)row * 256 + kq * 64 + kl2;
#pragma unroll
            for (int kt = 0; kt < 4; kt++) {
                bfr[nt][kt][0] = pk_bf2(wr[kt * 16],     wr[kt * 16 + 1]);
                bfr[nt][kt][1] = pk_bf2(wr[kt * 16 + 8], wr[kt * 16 + 9]);
            }
        }
    }

    const int u4 = tid >> 6, b = tid & 63;    // gate-math mapping (units u4, u4+4)
    float cst0 = 0.f, cst1 = 0.f;

    for (int t = 0; t < T_SEQ; t++) {
        // prefetch this block's gin: one contiguous 8KB row, coalesced
        const float4* gp = (const float4*)(g_gates + ((size_t)(bid * 256 + t)) * 2048)
                         + tid * 2;
        float4 ga = __ldg(gp), gb2 = __ldg(gp + 1);

        if (t > 0) {
            if (tid == 0) { while (ld_acq(&g_bar[t - 1]) < NBLK) {} }
            __syncthreads();
        }

        // stage gin to smem (scalar STS, pad-33 conflict-free)
        {
            float* gd = gsm + (tid >> 2) * 33 + (tid & 3) * 8;
            gd[0] = ga.x;  gd[1] = ga.y;  gd[2] = ga.z;  gd[3] = ga.w;
            gd[4] = gb2.x; gd[5] = gb2.y; gd[6] = gb2.z; gd[7] = gb2.w;
        }

        if (t > 0) {
            // load A fragments: 8 coalesced LDG.128/warp (32KB/block, L2)
            const uint4* hb = (const uint4*)(g_hb + ((((t - 1) & 1) * 2 + dir) << 13));
            uint4 aq[2][4];
#pragma unroll
            for (int kt = 0; kt < 4; kt++)
#pragma unroll
                for (int mt = 0; mt < 2; mt++)
                    aq[mt][kt] = ldcg_u4(hb + (((kq * 4 + kt) * 4 + mh * 2 + mt) << 5) + lane);

            float acc[2][4][4];
#pragma unroll
            for (int i = 0; i < 2; i++)
#pragma unroll
                for (int j = 0; j < 4; j++)
#pragma unroll
                    for (int q = 0; q < 4; q++) acc[i][j][q] = 0.f;

#pragma unroll
            for (int kt = 0; kt < 4; kt++)
#pragma unroll
                for (int mt = 0; mt < 2; mt++) {
                    uint32_t au[4] = { aq[mt][kt].x, aq[mt][kt].y, aq[mt][kt].z, aq[mt][kt].w };
#pragma unroll
                    for (int nt = 0; nt < 4; nt++)
                        mma16bf(acc[mt][nt], au, bfr[nt][kt]);
                }

            // store partials (conflict-free)
#pragma unroll
            for (int mt = 0; mt < 2; mt++)
#pragma unroll
                for (int nt = 0; nt < 4; nt++) {
                    int n0 = nt * 8 + (lane & 3) * 2;
                    int bb = mh * 32 + mt * 16 + (lane >> 2);
                    float* pp = psum + (kq * 32 + n0) * 68 + bb;
                    pp[0]      = acc[mt][nt][0];
                    pp[68]     = acc[mt][nt][1];
                    pp[8]      = acc[mt][nt][2];
                    pp[68 + 8] = acc[mt][nt][3];
                }
        }
        __syncthreads();

        // gate math: gin + 4 k-partials, MUFU activations, cell update
        float hout[2];
#pragma unroll
        for (int p = 0; p < 2; p++) {
            int u = u4 + 4 * p;
            const float* gr = gsm + b * 33 + u;
            float v0 = gr[0], v1 = gr[8], v2 = gr[16], v3 = gr[24];
            if (t > 0) {
                int n = u * 4;
#pragma unroll
                for (int q = 0; q < 4; q++) {
                    const float* pp = psum + (q * 32 + n) * 68 + b;
                    v0 += pp[0]; v1 += pp[68]; v2 += pp[2 * 68]; v3 += pp[3 * 68];
                }
            }
            float ci = siga(v0), cf = siga(v1), cg = tanha(v2), co = siga(v3);
            float cprev = p ? cst1 : cst0;
            float cc = cf * cprev + ci * cg;
            float hh = co * tanha(cc);
            if (p) cst1 = cc; else cst0 = cc;
            hsm[b * 9 + u] = hh;
            hout[p] = hh;
        }
        __syncthreads();

        // publish h(t) as bf16 fragments (this block's k-half of 4 btiles)
        if (tid < 128) {
            int bt = tid >> 5, l = tid & 31;
            int b0 = bt * 16 + (l >> 2), u2 = (l & 3) * 2;
            uint32_t lo = pk_bf2(hsm[b0 * 9 + u2],       hsm[b0 * 9 + u2 + 1]);
            uint32_t hi = pk_bf2(hsm[(b0 + 8) * 9 + u2], hsm[(b0 + 8) * 9 + u2 + 1]);
            uint32_t* out = g_hb + (((t & 1) * 2 + dir) << 13)
                          + (((j0 >> 4) * 4 + bt) << 7) + l * 4 + ((j0 & 8) >> 2);
            *(uint2*)out = make_uint2(lo, hi);
        }
        __syncthreads();
        if (tid == 0 && t < T_SEQ - 1)
            asm volatile("red.release.gpu.global.add.u32 [%0], 1;"
                         :: "l"(&g_bar[t]) : "memory");

        // deferred layer-output writes (off the release critical path)
        if (layer == 0) {
            if (tid < 128) {
                int b2 = tid >> 1, half = tid & 1;
                const float* hr = hsm + b2 * 9 + half * 4;
                float4 w4 = make_float4(hr[0], hr[1], hr[2], hr[3]);
                *(float4*)&g_x1[(size_t)((t << 6) + b2) * 512 + dir * 256 + j0 + half * 4] = w4;
            }
        } else {
            g_x2T[(size_t)(dir * 256 + j0 + u4) * MROWS + (t << 6) + b]       = hout[0];
            g_x2T[(size_t)(dir * 256 + j0 + u4 + 4) * MROWS + (t << 6) + b]   = hout[1];
        }
    }
}

// ---------------- classifier ----------------
__global__ void k_clf(const int* __restrict__ tidx, const float* __restrict__ cw,
                      const float* __restrict__ cb, float* __restrict__ out) {
    __shared__ float red[128];
    int b = blockIdx.x;
    int col = tidx[b] * BATCH + b;
    float s = 0.f;
    for (int k = threadIdx.x; k < 512; k += 128)
        s += g_x2T[(size_t)k * MROWS + col] * cw[k];
    red[threadIdx.x] = s;
    __syncthreads();
    for (int off = 64; off > 0; off >>= 1) {
        if (threadIdx.x < off) red[threadIdx.x] += red[threadIdx.x + off];
        __syncthreads();
    }
    if (threadIdx.x == 0) out[b] = 1.f / (1.f + expf(-(red[0] + cb[0])));
}

// ---------------- host ----------------
extern "C" void kernel_launch(void* const* d_in, const int* in_sizes, int n_in,
                              void* d_out, int out_size) {
    const int*   inp  = (const int*)  d_in[0];
    const int*   tidx = (const int*)  d_in[1];
    const float* emb  = (const float*)d_in[2];
    const float* wih0 = (const float*)d_in[3];
    const float* whh0 = (const float*)d_in[4];
    const float* bih0 = (const float*)d_in[5];
    const float* bhh0 = (const float*)d_in[6];
    const float* wih1 = (const float*)d_in[7];
    const float* whh1 = (const float*)d_in[8];
    const float* bih1 = (const float*)d_in[9];
    const float* bhh1 = (const float*)d_in[10];
    const float* clfw = (const float*)d_in[11];
    const float* clfb = (const float*)d_in[12];
    float* out = (float*)d_out;

    // layer 0
    k_padw<<<NGATE, 128>>>(wih0);
    k_embed<<<MROWS, 128>>>(inp, emb);
    k_gemm_tc<0><<<dim3(16, 128), 256>>>(nullptr, bih0, bhh0);   // also zeros g_bar
    k_lstm<<<NBLK, 256>>>(whh0, 0);

    // layer 1
    k_gemm_tc<1><<<dim3(16, 128), 256>>>(wih1, bih1, bhh1);      // also zeros g_bar
    k_lstm<<<NBLK, 256>>>(whh1, 1);

    // classifier
    k_clf<<<BATCH, 128>>>(tidx, clfw, clfb, out);
}

// round 7
// speedup vs baseline: 2.8603x; 1.1296x over previous
#include <cuda_runtime.h>
#include <cuda_fp16.h>
#include <math.h>
#include <stdint.h>

#define T_SEQ 256
#define BATCH 64
#define HID   256
#define NGATE 2048              // 2 dirs * 4H
#define MROWS (T_SEQ*BATCH)     // 16384
#define K0P   304               // padded input dim for layer 0 (300 -> 304)
#define NBLK  64                // persistent blocks in recurrent kernel

// ---------------- scratch (device globals; no allocation allowed) ----------------
__device__ __half   g_x0h[(size_t)MROWS * K0P];     // embedded input, fp16, padded
__device__ __half   g_w0h[NGATE * K0P];             // padded wih0, fp16
__device__ __half   g_w1h[NGATE * 512];             // wih1, fp16
// gates layout: [blk(64)][t(256)][b(64)][g*8+u(32)] halves  (blk = dir*32 + j0/8)
__device__ __half   g_gatesh[(size_t)MROWS * NGATE];
__device__ __half   g_x1h[(size_t)MROWS * 512];     // layer-0 output, row-major, fp16
__device__ float    g_x2T[(size_t)512 * MROWS];     // layer-1 output, feat-major f32
__device__ uint32_t g_hb[2 * 2 * 8192];             // double-buffered h, fp16 frag layout
__device__ unsigned g_bar[2 * T_SEQ];               // per-dir per-step barrier counters

// ---------------- numeric helpers ----------------
__device__ __forceinline__ uint32_t pk_h2(float lo, float hi) {
    __half2 h = __floats2half2_rn(lo, hi);
    return *(uint32_t*)&h;
}
__device__ __forceinline__ void mma16h(float* c, const uint32_t* a, const uint32_t* b) {
    asm volatile("mma.sync.aligned.m16n8k16.row.col.f32.f16.f16.f32 "
                 "{%0,%1,%2,%3},{%4,%5,%6,%7},{%8,%9},{%0,%1,%2,%3};"
                 : "+f"(c[0]), "+f"(c[1]), "+f"(c[2]), "+f"(c[3])
                 : "r"(a[0]), "r"(a[1]), "r"(a[2]), "r"(a[3]),
                   "r"(b[0]), "r"(b[1]));
}
__device__ __forceinline__ float tanha(float x) {
    float y; asm("tanh.approx.f32 %0, %1;" : "=f"(y) : "f"(x)); return y;
}
__device__ __forceinline__ float siga(float x) { return fmaf(0.5f, tanha(0.5f * x), 0.5f); }
__device__ __forceinline__ unsigned ld_acq(const unsigned* p) {
    unsigned v; asm volatile("ld.acquire.gpu.global.u32 %0, [%1];" : "=r"(v) : "l"(p)); return v;
}
__device__ __forceinline__ uint4 ldcg_u4(const uint4* p) {
    uint4 v;
    asm volatile("ld.global.cg.v4.u32 {%0,%1,%2,%3}, [%4];"
                 : "=r"(v.x), "=r"(v.y), "=r"(v.z), "=r"(v.w) : "l"(p));
    return v;
}

// ---------------- small kernels ----------------
__global__ void k_cvtw0(const float* __restrict__ w) {
    int n = blockIdx.x;
    __half* o = g_w0h + n * K0P;
    const float* s = w + n * 300;
    for (int k = threadIdx.x; k < K0P; k += blockDim.x)
        o[k] = (k < 300) ? __float2half(s[k]) : __half(0.f);
}
__global__ void k_cvtw1(const float* __restrict__ w) {
    int n = blockIdx.x;
    __half* o = g_w1h + n * 512;
    const float* s = w + n * 512;
    for (int k = threadIdx.x; k < 512; k += blockDim.x)
        o[k] = __float2half(s[k]);
}
__global__ void k_embed(const int* __restrict__ inp, const float* __restrict__ emb) {
    int m = blockIdx.x;            // m = t*64 + b
    int t = m >> 6, b = m & 63;
    int idx = inp[b * T_SEQ + t];
    const float* e = emb + (size_t)idx * 300;
    __half* o = g_x0h + (size_t)m * K0P;
    for (int k = threadIdx.x; k < K0P; k += blockDim.x)
        o[k] = (k < 300) ? __float2half(e[k]) : __half(0.f);
}

// ---------------- fp16 tensor-core GEMM (input projections) ----------------
// gates = A @ W^T + bi + bh, written as fp16 in scan-friendly layout.
template<int LAYER>
__global__ __launch_bounds__(256) void k_gemm_tc(const float* __restrict__ bi,
                                                 const float* __restrict__ bh) {
    constexpr int K = LAYER ? 512 : K0P;
    constexpr int NST = K / 16;
    const __half* A = LAYER ? g_x1h : g_x0h;
    const __half* W = LAYER ? g_w1h : g_w0h;

    // fold-in: zero the scan barriers for the following k_lstm launch
    if (blockIdx.x == 0 && blockIdx.y == 0) {
        g_bar[threadIdx.x] = 0u; g_bar[threadIdx.x + 256] = 0u;
    }

    __shared__ uint32_t As[2][1024];   // [mt(8)][reg(4)][lane(32)]
    __shared__ uint32_t Bs[2][1024];   // [ntile(16)][reg(2)][lane(32)]

    const int tid = threadIdx.x, lane = tid & 31, wid = tid >> 5;
    const int m0 = blockIdx.y << 7, n0 = blockIdx.x << 7;
    const int warp_m = wid & 1, warp_n = wid >> 1;   // warp tile 64(M) x 32(N)

    // loader: per thread 2 uint2 of A (4 halves each) and 2 of W per 16-k stage
    const __half *agp[2], *wgp[2];
    int aoff[2], boff[2];
#pragma unroll
    for (int e = 0; e < 2; e++) {
        int q = tid * 2 + e, row = q >> 2, kq = q & 3;
        agp[e] = A + (size_t)(m0 + row) * K + (kq << 2);
        wgp[e] = W + (size_t)(n0 + row) * K + (kq << 2);
        int p0 = kq * 2;
        aoff[e] = (((row >> 4) * 4 + (((row >> 3) & 1) | ((p0 >> 2) << 1))) << 5)
                + ((row & 7) << 2) + (p0 & 3);
        boff[e] = (((row >> 3) * 2 + (p0 >> 2)) << 5)
                + ((row & 7) << 2) + (p0 & 3);
    }

    float c[4][4][4];
#pragma unroll
    for (int i = 0; i < 4; i++)
#pragma unroll
        for (int j = 0; j < 4; j++)
#pragma unroll
            for (int q = 0; q < 4; q++) c[i][j][q] = 0.f;

    // prologue: stage 0
#pragma unroll
    for (int e = 0; e < 2; e++) {
        uint2 va = *(const uint2*)agp[e];
        uint2 vb = *(const uint2*)wgp[e];
        *(uint2*)&As[0][aoff[e]] = va;
        *(uint2*)&Bs[0][boff[e]] = vb;
    }
    __syncthreads();

    int buf = 0;
#pragma unroll 1
    for (int s = 0; s < NST; s++) {
        uint2 va[2], vb[2];
        const bool more = (s + 1) < NST;
        if (more) {
#pragma unroll
            for (int e = 0; e < 2; e++) {
                va[e] = *(const uint2*)(agp[e] + (s + 1) * 16);
                vb[e] = *(const uint2*)(wgp[e] + (s + 1) * 16);
            }
        }
        uint32_t af[4][4], bf[4][2];
#pragma unroll
        for (int mt = 0; mt < 4; mt++) {
            int tb = ((warp_m * 4 + mt) << 7) + lane;
#pragma unroll
            for (int r = 0; r < 4; r++) af[mt][r] = As[buf][tb + (r << 5)];
        }
#pragma unroll
        for (int nt = 0; nt < 4; nt++) {
            int tb = ((warp_n * 4 + nt) << 6) + lane;
            bf[nt][0] = Bs[buf][tb];
            bf[nt][1] = Bs[buf][tb + 32];
        }
#pragma unroll
        for (int mt = 0; mt < 4; mt++)
#pragma unroll
            for (int nt = 0; nt < 4; nt++)
                mma16h(c[mt][nt], af[mt], bf[nt]);

        if (more) {
            int nb = buf ^ 1;
#pragma unroll
            for (int e = 0; e < 2; e++) {
                *(uint2*)&As[nb][aoff[e]] = va[e];
                *(uint2*)&Bs[nb][boff[e]] = vb[e];
            }
            __syncthreads();
            buf = nb;
        }
    }

    // epilogue: fused bias, pack fp16x2, store to scan layout
    uint32_t* gout = (uint32_t*)g_gatesh;
#pragma unroll
    for (int nt = 0; nt < 4; nt++) {
        int n = n0 + warp_n * 32 + nt * 8 + (lane & 3) * 2;
        int dir = n >> 10, g = (n >> 8) & 3, j = n & 255;
        int blk = dir * 32 + (j >> 3), u = j & 7;
        float b0 = bi[n] + bh[n], b1 = bi[n + 1] + bh[n + 1];
        int inner = g * 4 + (u >> 1);          // u32 index within 16
#pragma unroll
        for (int mt = 0; mt < 4; mt++) {
            int r0 = m0 + warp_m * 64 + mt * 16 + (lane >> 2);
            int t = r0 >> 6, bb = r0 & 63;
            size_t base = ((size_t)(blk * 256 + t) * 64);
            gout[(base + bb) * 16 + inner]     = pk_h2(c[mt][nt][0] + b0, c[mt][nt][1] + b1);
            gout[(base + bb + 8) * 16 + inner] = pk_h2(c[mt][nt][2] + b0, c[mt][nt][3] + b1);
        }
    }
}

// ---------------- recurrent scan: fp16 tensor-core persistent kernel ----------------
// 64 blocks (32/dir, per-dir barrier). Block owns 8 hidden units (32 gate rows) x 64 b.
// W^T in registers as fp16 B-fragments; h exchanged in fp16 fragment-native layout.
__global__ __launch_bounds__(256, 1) void k_lstm(const float* __restrict__ whh, // [2048][256]
                                                 int layer) {
    __shared__ uint32_t gsm[64 * 17];     // staged fp16x2 input-gate terms, pad-17
    __shared__ float psum[4 * 32 * 68];   // k-split partials [kq][n][b]
    __shared__ float hsm[64 * 9];         // h(t) staging [b][u], pad-9

    const int tid = threadIdx.x, lane = tid & 31, wid = tid >> 5;
    const int bid = blockIdx.x;
    const int dir = bid >> 5;             // 0/1
    const int j0  = (bid & 31) << 3;      // 8 hidden units per block
    const int mh  = wid >> 2;             // batch half 0/1
    const int kq  = wid & 3;              // k quarter 0..3
    unsigned* barp = g_bar + dir * 256;

    // --- persistent B fragments: W^T slice, fp16, 32 regs ---
    uint32_t bfr[4][4][2];
    {
        const int nr = lane >> 2, kl2 = (lane & 3) * 2;
#pragma unroll
        for (int nt = 0; nt < 4; nt++) {
            int nn = nt * 8 + nr;                       // gate-row 0..31
            int row = dir * 1024 + (nn & 3) * 256 + j0 + (nn >> 2);
            const float* wr = whh + (size_t)row * 256 + kq * 64 + kl2;
#pragma unroll
            for (int kt = 0; kt < 4; kt++) {
                bfr[nt][kt][0] = pk_h2(wr[kt * 16],     wr[kt * 16 + 1]);
                bfr[nt][kt][1] = pk_h2(wr[kt * 16 + 8], wr[kt * 16 + 9]);
            }
        }
    }

    const int u4 = tid >> 6, b = tid & 63;    // gate-math mapping (units u4, u4+4)
    float cst0 = 0.f, cst1 = 0.f;

    for (int t = 0; t < T_SEQ; t++) {
        // prefetch this block's gin: 4KB contiguous (uint4 = 8 halves per thread),
        // and stage to smem BEFORE the spin (off the critical path)
        {
            uint4 g4 = __ldg((const uint4*)(g_gatesh + (size_t)(bid * 256 + t) * 2048) + tid);
            uint32_t* gd = gsm + (tid >> 2) * 17 + (tid & 3) * 4;
            gd[0] = g4.x; gd[1] = g4.y; gd[2] = g4.z; gd[3] = g4.w;
        }

        if (t > 0) {
            if (tid == 0) { while (ld_acq(&barp[t - 1]) < NBLK / 2) {} }
            __syncthreads();

            // load A fragments: 8 coalesced LDG.128/warp (32KB/block, L2)
            const uint4* hb = (const uint4*)(g_hb + ((((t - 1) & 1) * 2 + dir) << 13));
            uint4 aq[2][4];
#pragma unroll
            for (int kt = 0; kt < 4; kt++)
#pragma unroll
                for (int mt = 0; mt < 2; mt++)
                    aq[mt][kt] = ldcg_u4(hb + (((kq * 4 + kt) * 4 + mh * 2 + mt) << 5) + lane);

            float acc[2][4][4];
#pragma unroll
            for (int i = 0; i < 2; i++)
#pragma unroll
                for (int j = 0; j < 4; j++)
#pragma unroll
                    for (int q = 0; q < 4; q++) acc[i][j][q] = 0.f;

#pragma unroll
            for (int kt = 0; kt < 4; kt++)
#pragma unroll
                for (int mt = 0; mt < 2; mt++) {
                    uint32_t au[4] = { aq[mt][kt].x, aq[mt][kt].y, aq[mt][kt].z, aq[mt][kt].w };
#pragma unroll
                    for (int nt = 0; nt < 4; nt++)
                        mma16h(acc[mt][nt], au, bfr[nt][kt]);
                }

            // store partials (conflict-free)
#pragma unroll
            for (int mt = 0; mt < 2; mt++)
#pragma unroll
                for (int nt = 0; nt < 4; nt++) {
                    int n0 = nt * 8 + (lane & 3) * 2;
                    int bb = mh * 32 + mt * 16 + (lane >> 2);
                    float* pp = psum + (kq * 32 + n0) * 68 + bb;
                    pp[0]      = acc[mt][nt][0];
                    pp[68]     = acc[mt][nt][1];
                    pp[8]      = acc[mt][nt][2];
                    pp[68 + 8] = acc[mt][nt][3];
                }
        }
        __syncthreads();

        // gate math: gin + 4 k-partials, MUFU activations, cell update
        float hout[2];
#pragma unroll
        for (int p = 0; p < 2; p++) {
            int u = u4 + 4 * p;
            float v[4];
#pragma unroll
            for (int g = 0; g < 4; g++) {
                __half2 hv = *(__half2*)&gsm[b * 17 + g * 4 + 2 * p + (u4 >> 1)];
                float2 f2 = __half22float2(hv);
                v[g] = (u4 & 1) ? f2.y : f2.x;
            }
            if (t > 0) {
                int n = u * 4;
#pragma unroll
                for (int q = 0; q < 4; q++) {
                    const float* pp = psum + (q * 32 + n) * 68 + b;
                    v[0] += pp[0]; v[1] += pp[68]; v[2] += pp[2 * 68]; v[3] += pp[3 * 68];
                }
            }
            float ci = siga(v[0]), cf = siga(v[1]), cg = tanha(v[2]), co = siga(v[3]);
            float cprev = p ? cst1 : cst0;
            float cc = cf * cprev + ci * cg;
            float hh = co * tanha(cc);
            if (p) cst1 = cc; else cst0 = cc;
            hsm[b * 9 + u] = hh;
            hout[p] = hh;
        }
        __syncthreads();

        // publish h(t) as fp16 fragments
        if (tid < 128) {
            int bt = tid >> 5, l = tid & 31;
            int b0 = bt * 16 + (l >> 2), u2 = (l & 3) * 2;
            uint32_t lo = pk_h2(hsm[b0 * 9 + u2],       hsm[b0 * 9 + u2 + 1]);
            uint32_t hi = pk_h2(hsm[(b0 + 8) * 9 + u2], hsm[(b0 + 8) * 9 + u2 + 1]);
            uint32_t* out = g_hb + (((t & 1) * 2 + dir) << 13)
                          + (((j0 >> 4) * 4 + bt) << 7) + l * 4 + ((j0 & 8) >> 2);
            *(uint2*)out = make_uint2(lo, hi);
        }
        __syncthreads();
        if (tid == 0 && t < T_SEQ - 1)
            asm volatile("red.release.gpu.global.add.u32 [%0], 1;"
                         :: "l"(&barp[t]) : "memory");

        // deferred layer-output writes (off the release critical path)
        if (layer == 0) {
            if (tid < 128) {
                int b2 = tid >> 1, hs = tid & 1;
                const float* hr = hsm + b2 * 9 + hs * 4;
                uint2 w2 = make_uint2(pk_h2(hr[0], hr[1]), pk_h2(hr[2], hr[3]));
                *(uint2*)&g_x1h[(size_t)((t << 6) + b2) * 512 + dir * 256 + j0 + hs * 4] = w2;
            }
        } else {
            g_x2T[(size_t)(dir * 256 + j0 + u4) * MROWS + (t << 6) + b]     = hout[0];
            g_x2T[(size_t)(dir * 256 + j0 + u4 + 4) * MROWS + (t << 6) + b] = hout[1];
        }
    }
}

// ---------------- classifier ----------------
__global__ void k_clf(const int* __restrict__ tidx, const float* __restrict__ cw,
                      const float* __restrict__ cb, float* __restrict__ out) {
    __shared__ float red[128];
    int b = blockIdx.x;
    int col = tidx[b] * BATCH + b;
    float s = 0.f;
    for (int k = threadIdx.x; k < 512; k += 128)
        s += g_x2T[(size_t)k * MROWS + col] * cw[k];
    red[threadIdx.x] = s;
    __syncthreads();
    for (int off = 64; off > 0; off >>= 1) {
        if (threadIdx.x < off) red[threadIdx.x] += red[threadIdx.x + off];
        __syncthreads();
    }
    if (threadIdx.x == 0) out[b] = 1.f / (1.f + expf(-(red[0] + cb[0])));
}

// ---------------- host ----------------
extern "C" void kernel_launch(void* const* d_in, const int* in_sizes, int n_in,
                              void* d_out, int out_size) {
    const int*   inp  = (const int*)  d_in[0];
    const int*   tidx = (const int*)  d_in[1];
    const float* emb  = (const float*)d_in[2];
    const float* wih0 = (const float*)d_in[3];
    const float* whh0 = (const float*)d_in[4];
    const float* bih0 = (const float*)d_in[5];
    const float* bhh0 = (const float*)d_in[6];
    const float* wih1 = (const float*)d_in[7];
    const float* whh1 = (const float*)d_in[8];
    const float* bih1 = (const float*)d_in[9];
    const float* bhh1 = (const float*)d_in[10];
    const float* clfw = (const float*)d_in[11];
    const float* clfb = (const float*)d_in[12];
    float* out = (float*)d_out;

    // layer 0
    k_cvtw0<<<NGATE, 128>>>(wih0);
    k_cvtw1<<<NGATE, 128>>>(wih1);
    k_embed<<<MROWS, 128>>>(inp, emb);
    k_gemm_tc<0><<<dim3(16, 128), 256>>>(bih0, bhh0);   // also zeros g_bar
    k_lstm<<<NBLK, 256>>>(whh0, 0);

    // layer 1
    k_gemm_tc<1><<<dim3(16, 128), 256>>>(bih1, bhh1);   // also zeros g_bar
    k_lstm<<<NBLK, 256>>>(whh1, 1);

    // classifier
    k_clf<<<BATCH, 128>>>(tidx, clfw, clfb, out);
}

// round 9
// speedup vs baseline: 3.2561x; 1.1384x over previous
#include <cuda_runtime.h>
#include <cuda_fp16.h>
#include <math.h>
#include <stdint.h>

#define T_SEQ 256
#define BATCH 64
#define HID   256
#define NGATE 2048              // 2 dirs * 4H
#define MROWS (T_SEQ*BATCH)     // 16384
#define K0P   304               // padded input dim for layer 0 (300 -> 304)
#define NBLK_DIR 32             // persistent blocks per direction

// ---------------- scratch (device globals; no allocation allowed) ----------------
__device__ __half   g_x0h[(size_t)MROWS * K0P];     // embedded input, fp16, padded
__device__ __half   g_w0h[NGATE * K0P];             // padded wih0, fp16
__device__ __half   g_w1h[NGATE * 512];             // wih1, fp16
// gates layout: [blk(64)][t(256)][b(64)][g*8+u(32)] halves  (blk = dir*32 + j0/8)
__device__ __half   g_gatesh[(size_t)MROWS * NGATE];
// h history, fp16 fragment-native: [dir(2)][t(256)][8192 u32]
//   per (dir,t): 16 ktiles(16 units) x 4 btiles(16 b) x 128 u32 (m16n8k16 A-frag per lane)
__device__ uint32_t g_hb[(size_t)2 * T_SEQ * 8192];
__device__ unsigned g_bar[2 * T_SEQ];               // per-dir per-step barrier counters

// ---------------- numeric helpers ----------------
__device__ __forceinline__ uint32_t pk_h2(float lo, float hi) {
    __half2 h = __floats2half2_rn(lo, hi);
    return *(uint32_t*)&h;
}
__device__ __forceinline__ void mma16h(float* c, const uint32_t* a, const uint32_t* b) {
    asm volatile("mma.sync.aligned.m16n8k16.row.col.f32.f16.f16.f32 "
                 "{%0,%1,%2,%3},{%4,%5,%6,%7},{%8,%9},{%0,%1,%2,%3};"
                 : "+f"(c[0]), "+f"(c[1]), "+f"(c[2]), "+f"(c[3])
                 : "r"(a[0]), "r"(a[1]), "r"(a[2]), "r"(a[3]),
                   "r"(b[0]), "r"(b[1]));
}
__device__ __forceinline__ float tanha(float x) {
    float y; asm("tanh.approx.f32 %0, %1;" : "=f"(y) : "f"(x)); return y;
}
__device__ __forceinline__ float siga(float x) { return fmaf(0.5f, tanha(0.5f * x), 0.5f); }
__device__ __forceinline__ unsigned ld_acq(const unsigned* p) {
    unsigned v; asm volatile("ld.acquire.gpu.global.u32 %0, [%1];" : "=r"(v) : "l"(p)); return v;
}
__device__ __forceinline__ uint4 ldcg_u4(const uint4* p) {
    uint4 v;
    asm volatile("ld.global.cg.v4.u32 {%0,%1,%2,%3}, [%4];"
                 : "=r"(v.x), "=r"(v.y), "=r"(v.z), "=r"(v.w) : "l"(p));
    return v;
}

// ---------------- small kernels ----------------
__global__ void k_cvtw0(const float* __restrict__ w) {
    int n = blockIdx.x;
    __half* o = g_w0h + n * K0P;
    const float* s = w + n * 300;
    for (int k = threadIdx.x; k < K0P; k += blockDim.x)
        o[k] = (k < 300) ? __float2half(s[k]) : __half(0.f);
}
__global__ void k_cvtw1(const float* __restrict__ w) {
    int n = blockIdx.x;
    __half* o = g_w1h + n * 512;
    const float* s = w + n * 512;
    for (int k = threadIdx.x; k < 512; k += blockDim.x)
        o[k] = __float2half(s[k]);
}
__global__ void k_embed(const int* __restrict__ inp, const float* __restrict__ emb) {
    int m = blockIdx.x;            // m = t*64 + b
    int t = m >> 6, b = m & 63;
    int idx = inp[b * T_SEQ + t];
    const float* e = emb + (size_t)idx * 300;
    __half* o = g_x0h + (size_t)m * K0P;
    for (int k = threadIdx.x; k < K0P; k += blockDim.x)
        o[k] = (k < 300) ? __float2half(e[k]) : __half(0.f);
}

// ---------------- GEMM epilogue: store to scan-friendly fp16 gates layout ----------
__device__ __forceinline__ void gates_store(float c[4][4][4], const float* bi,
                                            const float* bh, int m0, int n0,
                                            int warp_m, int warp_n, int lane) {
    uint32_t* gout = (uint32_t*)g_gatesh;
#pragma unroll
    for (int nt = 0; nt < 4; nt++) {
        int n = n0 + warp_n * 32 + nt * 8 + (lane & 3) * 2;
        int dir = n >> 10, g = (n >> 8) & 3, j = n & 255;
        int blk = dir * 32 + (j >> 3), u = j & 7;
        float b0 = bi[n] + bh[n], b1 = bi[n + 1] + bh[n + 1];
        int inner = g * 4 + (u >> 1);          // u32 index within 16
#pragma unroll
        for (int mt = 0; mt < 4; mt++) {
            int r0 = m0 + warp_m * 64 + mt * 16 + (lane >> 2);
            int t = r0 >> 6, bb = r0 & 63;
            size_t base = ((size_t)(blk * 256 + t) * 64);
            gout[(base + bb) * 16 + inner]     = pk_h2(c[mt][nt][0] + b0, c[mt][nt][1] + b1);
            gout[(base + bb + 8) * 16 + inner] = pk_h2(c[mt][nt][2] + b0, c[mt][nt][3] + b1);
        }
    }
}

// ---------------- fp16 GEMM, layer 0 (A = g_x0h via smem) ----------------
__global__ __launch_bounds__(256) void k_gemm0(const float* __restrict__ bi,
                                               const float* __restrict__ bh) {
    constexpr int K = K0P;
    constexpr int NST = K / 16;
    const __half* A = g_x0h;
    const __half* W = g_w0h;

    if (blockIdx.x == 0 && blockIdx.y == 0) {      // zero scan barriers
        g_bar[threadIdx.x] = 0u; g_bar[threadIdx.x + 256] = 0u;
    }

    __shared__ uint32_t As[2][1024];
    __shared__ uint32_t Bs[2][1024];

    const int tid = threadIdx.x, lane = tid & 31, wid = tid >> 5;
    const int m0 = blockIdx.y << 7, n0 = blockIdx.x << 7;
    const int warp_m = wid & 1, warp_n = wid >> 1;

    const __half *agp[2], *wgp[2];
    int aoff[2], boff[2];
#pragma unroll
    for (int e = 0; e < 2; e++) {
        int q = tid * 2 + e, row = q >> 2, kq = q & 3;
        agp[e] = A + (size_t)(m0 + row) * K + (kq << 2);
        wgp[e] = W + (size_t)(n0 + row) * K + (kq << 2);
        int p0 = kq * 2;
        aoff[e] = (((row >> 4) * 4 + (((row >> 3) & 1) | ((p0 >> 2) << 1))) << 5)
                + ((row & 7) << 2) + (p0 & 3);
        boff[e] = (((row >> 3) * 2 + (p0 >> 2)) << 5) + ((row & 7) << 2) + (p0 & 3);
    }

    float c[4][4][4];
#pragma unroll
    for (int i = 0; i < 4; i++)
#pragma unroll
        for (int j = 0; j < 4; j++)
#pragma unroll
            for (int q = 0; q < 4; q++) c[i][j][q] = 0.f;

#pragma unroll
    for (int e = 0; e < 2; e++) {
        *(uint2*)&As[0][aoff[e]] = *(const uint2*)agp[e];
        *(uint2*)&Bs[0][boff[e]] = *(const uint2*)wgp[e];
    }
    __syncthreads();

    int buf = 0;
#pragma unroll 1
    for (int s = 0; s < NST; s++) {
        uint2 va[2], vb[2];
        const bool more = (s + 1) < NST;
        if (more) {
#pragma unroll
            for (int e = 0; e < 2; e++) {
                va[e] = *(const uint2*)(agp[e] + (s + 1) * 16);
                vb[e] = *(const uint2*)(wgp[e] + (s + 1) * 16);
            }
        }
        uint32_t af[4][4], bf[4][2];
#pragma unroll
        for (int mt = 0; mt < 4; mt++) {
            int tb = ((warp_m * 4 + mt) << 7) + lane;
#pragma unroll
            for (int r = 0; r < 4; r++) af[mt][r] = As[buf][tb + (r << 5)];
        }
#pragma unroll
        for (int nt = 0; nt < 4; nt++) {
            int tb = ((warp_n * 4 + nt) << 6) + lane;
            bf[nt][0] = Bs[buf][tb];
            bf[nt][1] = Bs[buf][tb + 32];
        }
#pragma unroll
        for (int mt = 0; mt < 4; mt++)
#pragma unroll
            for (int nt = 0; nt < 4; nt++)
                mma16h(c[mt][nt], af[mt], bf[nt]);

        if (more) {
            int nb = buf ^ 1;
#pragma unroll
            for (int e = 0; e < 2; e++) {
                *(uint2*)&As[nb][aoff[e]] = va[e];
                *(uint2*)&Bs[nb][boff[e]] = vb[e];
            }
            __syncthreads();
            buf = nb;
        }
    }
    gates_store(c, bi, bh, m0, n0, warp_m, warp_n, lane);
}

// ---------------- fp16 GEMM, layer 1 (A = fragment-native h history, no A smem) ----
__global__ __launch_bounds__(256) void k_gemm1(const float* __restrict__ bi,
                                               const float* __restrict__ bh) {
    constexpr int NST = 32;   // K = 512
    const __half* W = g_w1h;

    if (blockIdx.x == 0 && blockIdx.y == 0) {      // zero scan barriers
        g_bar[threadIdx.x] = 0u; g_bar[threadIdx.x + 256] = 0u;
    }

    __shared__ uint32_t Bs[2][1024];

    const int tid = threadIdx.x, lane = tid & 31, wid = tid >> 5;
    const int m0 = blockIdx.y << 7, n0 = blockIdx.x << 7;
    const int warp_m = wid & 1, warp_n = wid >> 1;

    const __half* wgp[2];
    int boff[2];
#pragma unroll
    for (int e = 0; e < 2; e++) {
        int q = tid * 2 + e, row = q >> 2, kq = q & 3;
        wgp[e] = W + (size_t)(n0 + row) * 512 + (kq << 2);
        int p0 = kq * 2;
        boff[e] = (((row >> 3) * 2 + (p0 >> 2)) << 5) + ((row & 7) << 2) + (p0 & 3);
    }

    // A-fragment address: ktile kt (0..31): dir=kt>>4, ut=kt&15; mtile idx=warp_m*4+mt
    const int ty0 = 2 * blockIdx.y;
    auto aptr = [&](int kt, int mt) -> const uint4* {
        int idx = warp_m * 4 + mt;
        return (const uint4*)(g_hb
            + ((size_t)((kt >> 4) * 256 + ty0 + (idx >> 2)) << 13)
            + (((kt & 15) * 4 + (idx & 3)) << 7)) + lane;
    };

    float c[4][4][4];
#pragma unroll
    for (int i = 0; i < 4; i++)
#pragma unroll
        for (int j = 0; j < 4; j++)
#pragma unroll
            for (int q = 0; q < 4; q++) c[i][j][q] = 0.f;

#pragma unroll
    for (int e = 0; e < 2; e++)
        *(uint2*)&Bs[0][boff[e]] = *(const uint2*)wgp[e];
    uint4 afc[4];
#pragma unroll
    for (int mt = 0; mt < 4; mt++) afc[mt] = __ldg(aptr(0, mt));
    __syncthreads();

    int buf = 0;
#pragma unroll 1
    for (int s = 0; s < NST; s++) {
        uint2 vb[2];
        uint4 afn[4];
        const bool more = (s + 1) < NST;
        if (more) {
#pragma unroll
            for (int e = 0; e < 2; e++) vb[e] = *(const uint2*)(wgp[e] + (s + 1) * 16);
#pragma unroll
            for (int mt = 0; mt < 4; mt++) afn[mt] = __ldg(aptr(s + 1, mt));
        }
        uint32_t bf[4][2];
#pragma unroll
        for (int nt = 0; nt < 4; nt++) {
            int tb = ((warp_n * 4 + nt) << 6) + lane;
            bf[nt][0] = Bs[buf][tb];
            bf[nt][1] = Bs[buf][tb + 32];
        }
#pragma unroll
        for (int mt = 0; mt < 4; mt++) {
            uint32_t af[4] = { afc[mt].x, afc[mt].y, afc[mt].z, afc[mt].w };
#pragma unroll
            for (int nt = 0; nt < 4; nt++)
                mma16h(c[mt][nt], af, bf[nt]);
        }
        if (more) {
            int nb = buf ^ 1;
#pragma unroll
            for (int e = 0; e < 2; e++) *(uint2*)&Bs[nb][boff[e]] = vb[e];
            __syncthreads();
            buf = nb;
#pragma unroll
            for (int mt = 0; mt < 4; mt++) afc[mt] = afn[mt];
        }
    }
    gates_store(c, bi, bh, m0, n0, warp_m, warp_n, lane);
}

// ---------------- recurrent scan: fp16 tc persistent kernel, history exchange ------
// 64 blocks (32/dir). Block: 8 hidden units (32 gate rows) x 64 batches.
// Publish = direct fragment STG into history (also the layer output). Per-warp poll.
__global__ __launch_bounds__(256, 1) void k_lstm(const float* __restrict__ whh) {
    __shared__ uint32_t gsm[2][64 * 17];  // double-buffered gin staging, pad-17
    __shared__ float psum[4 * 32 * 68];   // k-split partials [kq][nn][b], nn = u*4+g

    const int tid = threadIdx.x, lane = tid & 31, wid = tid >> 5;
    const int bid = blockIdx.x;
    const int dir = bid >> 5;
    const int j0  = (bid & 31) << 3;      // 8 hidden units per block
    const int mh  = wid >> 2;             // batch half
    const int kq  = wid & 3;              // k quarter
    unsigned* barp = g_bar + dir * 256;

    // persistent B fragments: W^T slice, fp16, 32 regs.  psum row nn: gate=nn&3, unit=nn>>2
    uint32_t bfr[4][4][2];
    {
        const int nr = lane >> 2, kl2 = (lane & 3) * 2;
#pragma unroll
        for (int nt = 0; nt < 4; nt++) {
            int nn = nt * 8 + nr;
            int row = dir * 1024 + (nn & 3) * 256 + j0 + (nn >> 2);
            const float* wr = whh + (size_t)row * 256 + kq * 64 + kl2;
#pragma unroll
            for (int kt = 0; kt < 4; kt++) {
                bfr[nt][kt][0] = pk_h2(wr[kt * 16],     wr[kt * 16 + 1]);
                bfr[nt][kt][1] = pk_h2(wr[kt * 16 + 8], wr[kt * 16 + 9]);
            }
        }
    }

    // gate-math mapping: thread (p, b) owns units j0+2p, j0+2p+1 for batch b
    const int p = tid >> 6, b = tid & 63;
    float cst0 = 0.f, cst1 = 0.f;
    // publish address (one u32 per thread per step; fragment slot math)
    uint32_t* pub = g_hb + ((size_t)(dir * 256) << 13)
                  + (((j0 >> 4) * 4 + (b >> 4)) << 7)
                  + (((b & 7) << 2) + p) * 4
                  + (((b & 8) >> 3) + ((j0 & 8) >> 2));
    const uint4* gb4 = (const uint4*)g_gatesh + (size_t)(bid * 256) * 256;

    // prologue: stage gin(0)
    {
        uint4 g4 = __ldg(gb4 + tid);
        uint32_t* gd = gsm[0] + (tid >> 2) * 17 + (tid & 3) * 4;
        gd[0] = g4.x; gd[1] = g4.y; gd[2] = g4.z; gd[3] = g4.w;
    }

    for (int t = 0; t < T_SEQ; t++) {
        // prefetch gin(t+1) (DRAM; fully off critical path)
        int tn = (t + 1 < T_SEQ) ? t + 1 : T_SEQ - 1;
        uint4 g4 = __ldg(gb4 + tn * 256 + tid);

        uint4 aq[2][4];
        if (t > 0) {
            // per-warp poll: all lanes spin on the per-dir flag, then load immediately
            while (ld_acq(&barp[t - 1]) < NBLK_DIR) {}
            const uint4* hb = (const uint4*)(g_hb + ((size_t)(dir * 256 + t - 1) << 13));
#pragma unroll
            for (int kt = 0; kt < 4; kt++)
#pragma unroll
                for (int mt = 0; mt < 2; mt++)
                    aq[mt][kt] = ldcg_u4(hb + (((kq * 4 + kt) * 4 + mh * 2 + mt) << 5) + lane);
        }

        // stage gin(t+1) into the other buffer (overlaps A-load latency)
        {
            uint32_t* gd = gsm[(t + 1) & 1] + (tid >> 2) * 17 + (tid & 3) * 4;
            gd[0] = g4.x; gd[1] = g4.y; gd[2] = g4.z; gd[3] = g4.w;
        }

        if (t > 0) {
            float acc[2][4][4];
#pragma unroll
            for (int i = 0; i < 2; i++)
#pragma unroll
                for (int j = 0; j < 4; j++)
#pragma unroll
                    for (int q = 0; q < 4; q++) acc[i][j][q] = 0.f;
#pragma unroll
            for (int kt = 0; kt < 4; kt++)
#pragma unroll
                for (int mt = 0; mt < 2; mt++) {
                    uint32_t au[4] = { aq[mt][kt].x, aq[mt][kt].y, aq[mt][kt].z, aq[mt][kt].w };
#pragma unroll
                    for (int nt = 0; nt < 4; nt++)
                        mma16h(acc[mt][nt], au, bfr[nt][kt]);
                }
#pragma unroll
            for (int mt = 0; mt < 2; mt++)
#pragma unroll
                for (int nt = 0; nt < 4; nt++) {
                    int n0 = nt * 8 + (lane & 3) * 2;
                    int bb = mh * 32 + mt * 16 + (lane >> 2);
                    float* pp = psum + (kq * 32 + n0) * 68 + bb;
                    pp[0]      = acc[mt][nt][0];
                    pp[68]     = acc[mt][nt][1];
                    pp[8]      = acc[mt][nt][2];
                    pp[68 + 8] = acc[mt][nt][3];
                }
        }
        __syncthreads();   // psum + gsm(t) ready

        // gate math for units 2p, 2p+1 of batch b
        float v[4][2];
#pragma unroll
        for (int g = 0; g < 4; g++) {
            __half2 hv = *(__half2*)&gsm[t & 1][b * 17 + g * 4 + p];
            float2 f2 = __half22float2(hv);
            v[g][0] = f2.x; v[g][1] = f2.y;
        }
        if (t > 0) {
            // FIXED: psum row for (unit u, gate g) is nn = u*4 + g
            //   unit 2p   -> nn = 8p + g
            //   unit 2p+1 -> nn = 8p + 4 + g
#pragma unroll
            for (int g = 0; g < 4; g++) {
                int r0 = 8 * p + g;
#pragma unroll
                for (int q = 0; q < 4; q++) {
                    v[g][0] += psum[(q * 32 + r0) * 68 + b];
                    v[g][1] += psum[(q * 32 + r0 + 4) * 68 + b];
                }
            }
        }
        float h0, h1;
        {
            float ci = siga(v[0][0]), cf = siga(v[1][0]), cg = tanha(v[2][0]), co = siga(v[3][0]);
            cst0 = cf * cst0 + ci * cg;
            h0 = co * tanha(cst0);
            ci = siga(v[0][1]); cf = siga(v[1][1]); cg = tanha(v[2][1]); co = siga(v[3][1]);
            cst1 = cf * cst1 + ci * cg;
            h1 = co * tanha(cst1);
        }
        // publish: one fragment u32 directly into history (exchange + layer output)
        pub[(size_t)t << 13] = pk_h2(h0, h1);
        __syncthreads();   // all publish STGs issued
        if (tid == 0 && t < T_SEQ - 1)
            asm volatile("red.release.gpu.global.add.u32 [%0], 1;"
                         :: "l"(&barp[t]) : "memory");
    }
}

// ---------------- classifier: gather from layer-1 history ----------------
__global__ void k_clf(const int* __restrict__ tidx, const float* __restrict__ cw,
                      const float* __restrict__ cb, float* __restrict__ out) {
    __shared__ float red[128];
    int b = blockIdx.x;
    int t = tidx[b];
    const __half* hist = (const __half*)g_hb;
    float s = 0.f;
    for (int f = threadIdx.x; f < 512; f += 128) {
        int dir = f >> 8, u = f & 255;
        int ut = u >> 4, k16 = u & 15;
        int l = ((b & 7) << 2) + ((k16 & 7) >> 1);
        int sl = ((b & 8) >> 3) + ((k16 & 8) >> 2);
        size_t u32i = ((size_t)(dir * 256 + t) << 13) + (((ut << 2) + (b >> 4)) << 7)
                    + l * 4 + sl;
        s += __half2float(hist[u32i * 2 + (k16 & 1)]) * cw[f];
    }
    red[threadIdx.x] = s;
    __syncthreads();
    for (int off = 64; off > 0; off >>= 1) {
        if (threadIdx.x < off) red[threadIdx.x] += red[threadIdx.x + off];
        __syncthreads();
    }
    if (threadIdx.x == 0) out[b] = 1.f / (1.f + expf(-(red[0] + cb[0])));
}

// ---------------- host ----------------
extern "C" void kernel_launch(void* const* d_in, const int* in_sizes, int n_in,
                              void* d_out, int out_size) {
    const int*   inp  = (const int*)  d_in[0];
    const int*   tidx = (const int*)  d_in[1];
    const float* emb  = (const float*)d_in[2];
    const float* wih0 = (const float*)d_in[3];
    const float* whh0 = (const float*)d_in[4];
    const float* bih0 = (const float*)d_in[5];
    const float* bhh0 = (const float*)d_in[6];
    const float* wih1 = (const float*)d_in[7];
    const float* whh1 = (const float*)d_in[8];
    const float* bih1 = (const float*)d_in[9];
    const float* bhh1 = (const float*)d_in[10];
    const float* clfw = (const float*)d_in[11];
    const float* clfb = (const float*)d_in[12];
    float* out = (float*)d_out;

    // layer 0
    k_cvtw0<<<NGATE, 128>>>(wih0);
    k_cvtw1<<<NGATE, 128>>>(wih1);
    k_embed<<<MROWS, 128>>>(inp, emb);
    k_gemm0<<<dim3(16, 128), 256>>>(bih0, bhh0);     // also zeros g_bar
    k_lstm<<<2 * NBLK_DIR, 256>>>(whh0);             // writes h history

    // layer 1 (GEMM A = layer-0 history fragments)
    k_gemm1<<<dim3(16, 128), 256>>>(bih1, bhh1);     // also zeros g_bar
    k_lstm<<<2 * NBLK_DIR, 256>>>(whh1);             // overwrites history with layer-1 h

    // classifier gathers from layer-1 history
    k_clf<<<BATCH, 128>>>(tidx, clfw, clfb, out);
}